// round 2
// baseline (speedup 1.0000x reference)
#include <cuda_runtime.h>

#define NUM_TOKENS 8192
#define HIDDEN 4096
#define NUM_EXPERTS 8
#define INTER 2048
#define GU_COLS 4096  /* 2 * INTER */

#define BM 64
#define BN 64
#define BK 16

// ---------------- scratch (device globals; no allocation allowed) ----------------
__device__ int   g_counts[NUM_EXPERTS];
__device__ int   g_lists[NUM_EXPERTS][NUM_TOKENS];
__device__ int   g_is64;  // 1 if token_ids buffer is int64-laid-out, 0 if int32
__device__ float g_inter[(size_t)NUM_TOKENS * INTER];  // 64 MB intermediate

// ---------------- routing ----------------
// Token values are in [0, 32000). If the buffer is int64 (little-endian), every
// odd 32-bit word is a zero high-word. If it's int32, odd words are token ids
// (essentially never all zero). Sample the odd words to decide.
__global__ void detect_kernel(const int* __restrict__ t32) {
    if (threadIdx.x == 0) {
        int all_zero = 1;
        // sample 256 odd words spread across the buffer
        for (int i = 0; i < 256; i++) {
            int idx = 2 * (i * (NUM_TOKENS / 256)) + 1;
            if (t32[idx] != 0) { all_zero = 0; break; }
        }
        g_is64 = all_zero;
    }
    if (threadIdx.x < NUM_EXPERTS) g_counts[threadIdx.x] = 0;
}

__global__ void route_kernel(const int* __restrict__ t32) {
    int i = blockIdx.x * blockDim.x + threadIdx.x;
    if (i < NUM_TOKENS) {
        int v = g_is64 ? t32[2 * i] : t32[i];  // low word either way
        int e = v & 7;                         // clip is a no-op; % 8 of nonneg
        int p = atomicAdd(&g_counts[e], 1);
        g_lists[e][p] = i;
    }
}

// ---------------- GEMM1: X_e[count x 4096] @ GU[e][4096 x 4096] -> fused SiLU*up -> g_inter ----------------
// Each block computes a BM x BN tile of BOTH gate (cols [n0,n0+BN)) and up (cols [n0+INTER, ...)),
// so the epilogue fuses silu(gate)*up without a second pass.
__global__ __launch_bounds__(256) void gemm1_kernel(const float* __restrict__ x,
                                                    const float* __restrict__ gup) {
    const int e = blockIdx.z;
    const int count = g_counts[e];
    const int m0 = blockIdx.y * BM;
    if (m0 >= count) return;
    const int n0 = blockIdx.x * BN;  // within INTER

    __shared__ int   tok[BM];
    __shared__ float As[BK][BM + 4];
    __shared__ float Bg[BK][BN];
    __shared__ float Bu[BK][BN];

    const int tid = threadIdx.x;
    if (tid < BM) tok[tid] = (m0 + tid < count) ? g_lists[e][m0 + tid] : -1;
    __syncthreads();

    const float* B = gup + (size_t)e * HIDDEN * GU_COLS;

    // A-load mapping: each thread loads one float4 along K for one row
    const int a_m = tid >> 2;          // 0..63
    const int a_k = (tid & 3) * 4;     // 0,4,8,12
    const int a_tok = tok[a_m];
    const float* a_ptr = (a_tok >= 0) ? (x + (size_t)a_tok * HIDDEN + a_k) : nullptr;

    // B-load mapping: each thread loads one float4 along N for one k-row
    const int b_k = tid >> 4;          // 0..15
    const int b_n = (tid & 15) * 4;
    const float* bg_ptr = B + (size_t)b_k * GU_COLS + n0 + b_n;
    const float* bu_ptr = bg_ptr + INTER;

    // compute mapping: 16x16 threads, each 4(m) x 4(n)
    const int tn = (tid & 15) * 4;
    const int tm = (tid >> 4) * 4;

    float accg[4][4] = {};
    float accu[4][4] = {};

    for (int k0 = 0; k0 < HIDDEN; k0 += BK) {
        float4 av = make_float4(0.f, 0.f, 0.f, 0.f);
        if (a_ptr) av = *(const float4*)(a_ptr + k0);
        const float4 bg = *(const float4*)(bg_ptr + (size_t)k0 * GU_COLS);
        const float4 bu = *(const float4*)(bu_ptr + (size_t)k0 * GU_COLS);

        __syncthreads();
        As[a_k + 0][a_m] = av.x;
        As[a_k + 1][a_m] = av.y;
        As[a_k + 2][a_m] = av.z;
        As[a_k + 3][a_m] = av.w;
        *(float4*)&Bg[b_k][b_n] = bg;
        *(float4*)&Bu[b_k][b_n] = bu;
        __syncthreads();

#pragma unroll
        for (int k = 0; k < BK; k++) {
            float a[4];
#pragma unroll
            for (int i = 0; i < 4; i++) a[i] = As[k][tm + i];
            const float4 bgv = *(const float4*)&Bg[k][tn];
            const float4 buv = *(const float4*)&Bu[k][tn];
            const float bgr[4] = {bgv.x, bgv.y, bgv.z, bgv.w};
            const float bur[4] = {buv.x, buv.y, buv.z, buv.w};
#pragma unroll
            for (int i = 0; i < 4; i++) {
#pragma unroll
                for (int j = 0; j < 4; j++) {
                    accg[i][j] += a[i] * bgr[j];
                    accu[i][j] += a[i] * bur[j];
                }
            }
        }
    }

    // fused epilogue: inter = silu(gate) * up, scattered to token rows
#pragma unroll
    for (int i = 0; i < 4; i++) {
        const int gtok = tok[tm + i];
        if (gtok < 0) continue;
        float4 v;
        float r[4];
#pragma unroll
        for (int j = 0; j < 4; j++) {
            const float g = accg[i][j];
            const float s = g / (1.0f + __expf(-g));
            r[j] = s * accu[i][j];
        }
        v.x = r[0]; v.y = r[1]; v.z = r[2]; v.w = r[3];
        *(float4*)(g_inter + (size_t)gtok * INTER + n0 + tn) = v;
    }
}

// ---------------- GEMM2: inter_e[count x 2048] @ Down[e][2048 x 4096] -> out (scatter) ----------------
__global__ __launch_bounds__(256) void gemm2_kernel(const float* __restrict__ down,
                                                    float* __restrict__ out) {
    const int e = blockIdx.z;
    const int count = g_counts[e];
    const int m0 = blockIdx.y * BM;
    if (m0 >= count) return;
    const int n0 = blockIdx.x * BN;

    __shared__ int   tok[BM];
    __shared__ float As[BK][BM + 4];
    __shared__ float Bs[BK][BN];

    const int tid = threadIdx.x;
    if (tid < BM) tok[tid] = (m0 + tid < count) ? g_lists[e][m0 + tid] : -1;
    __syncthreads();

    const float* B = down + (size_t)e * INTER * HIDDEN;

    const int a_m = tid >> 2;
    const int a_k = (tid & 3) * 4;
    const int a_tok = tok[a_m];
    const float* a_ptr = (a_tok >= 0) ? (g_inter + (size_t)a_tok * INTER + a_k) : nullptr;

    const int b_k = tid >> 4;
    const int b_n = (tid & 15) * 4;
    const float* b_ptr = B + (size_t)b_k * HIDDEN + n0 + b_n;

    const int tn = (tid & 15) * 4;
    const int tm = (tid >> 4) * 4;

    float acc[4][4] = {};

    for (int k0 = 0; k0 < INTER; k0 += BK) {
        float4 av = make_float4(0.f, 0.f, 0.f, 0.f);
        if (a_ptr) av = *(const float4*)(a_ptr + k0);
        const float4 bv = *(const float4*)(b_ptr + (size_t)k0 * HIDDEN);

        __syncthreads();
        As[a_k + 0][a_m] = av.x;
        As[a_k + 1][a_m] = av.y;
        As[a_k + 2][a_m] = av.z;
        As[a_k + 3][a_m] = av.w;
        *(float4*)&Bs[b_k][b_n] = bv;
        __syncthreads();

#pragma unroll
        for (int k = 0; k < BK; k++) {
            float a[4];
#pragma unroll
            for (int i = 0; i < 4; i++) a[i] = As[k][tm + i];
            const float4 bvv = *(const float4*)&Bs[k][tn];
            const float br[4] = {bvv.x, bvv.y, bvv.z, bvv.w};
#pragma unroll
            for (int i = 0; i < 4; i++) {
#pragma unroll
                for (int j = 0; j < 4; j++) acc[i][j] += a[i] * br[j];
            }
        }
    }

#pragma unroll
    for (int i = 0; i < 4; i++) {
        const int gtok = tok[tm + i];
        if (gtok < 0) continue;
        float4 v;
        v.x = acc[i][0]; v.y = acc[i][1]; v.z = acc[i][2]; v.w = acc[i][3];
        *(float4*)(out + (size_t)gtok * HIDDEN + n0 + tn) = v;
    }
}

// ---------------- launch ----------------
extern "C" void kernel_launch(void* const* d_in, const int* in_sizes, int n_in,
                              void* d_out, int out_size) {
    const float* x    = (const float*)d_in[0];
    const int*   tids = (const int*)d_in[1];   // int32 view; layout auto-detected
    const float* gup  = (const float*)d_in[2];
    const float* down = (const float*)d_in[3];
    float*       out  = (float*)d_out;

    detect_kernel<<<1, 32>>>(tids);
    route_kernel<<<NUM_TOKENS / 256, 256>>>(tids);

    // GEMM1: grid over (INTER tiles, token tiles, experts); inactive tiles exit immediately
    gemm1_kernel<<<dim3(INTER / BN, NUM_TOKENS / BM, NUM_EXPERTS), 256>>>(x, gup);
    // GEMM2
    gemm2_kernel<<<dim3(HIDDEN / BN, NUM_TOKENS / BM, NUM_EXPERTS), 256>>>(down, out);
}

// round 4
// speedup vs baseline: 2.5675x; 2.5675x over previous
#include <cuda_runtime.h>
#include <cstdint>

#define NUM_TOKENS 8192
#define HIDDEN 4096
#define NUM_EXPERTS 8
#define INTER 2048
#define GU_COLS 4096

// ---------------- scratch ----------------
__device__ int   g_counts[NUM_EXPERTS];
__device__ int   g_lists[NUM_EXPERTS][NUM_TOKENS];
__device__ int   g_is64;
__device__ float g_inter[(size_t)NUM_TOKENS * INTER];

// ---------------- helpers ----------------
__device__ __forceinline__ uint32_t smem_u32(const void* p) {
    uint32_t a;
    asm("{ .reg .u64 t; cvta.to.shared.u64 t, %1; cvt.u32.u64 %0, t; }" : "=r"(a) : "l"(p));
    return a;
}
__device__ __forceinline__ uint32_t f2tf(float f) {
    uint32_t r;
    asm("cvt.rna.tf32.f32 %0, %1;" : "=r"(r) : "f"(f));
    return r;
}
__device__ __forceinline__ void mma8(float* d, const uint32_t* a, uint32_t b0, uint32_t b1) {
    asm volatile(
        "mma.sync.aligned.m16n8k8.row.col.f32.tf32.tf32.f32 "
        "{%0,%1,%2,%3},{%4,%5,%6,%7},{%8,%9},{%0,%1,%2,%3};"
        : "+f"(d[0]), "+f"(d[1]), "+f"(d[2]), "+f"(d[3])
        : "r"(a[0]), "r"(a[1]), "r"(a[2]), "r"(a[3]), "r"(b0), "r"(b1));
}
__device__ __forceinline__ void cpa16(uint32_t dst, const void* src, int srcsize) {
    asm volatile("cp.async.cg.shared.global [%0], [%1], 16, %2;" :: "r"(dst), "l"(src), "r"(srcsize));
}
__device__ __forceinline__ void cpa_commit() { asm volatile("cp.async.commit_group;" ::: "memory"); }
__device__ __forceinline__ void cpa_wait1()  { asm volatile("cp.async.wait_group 1;" ::: "memory"); }
__device__ __forceinline__ void cpa_wait0()  { asm volatile("cp.async.wait_group 0;" ::: "memory"); }

__device__ __forceinline__ float silu(float g) { return g / (1.0f + __expf(-g)); }

// ---------------- routing ----------------
__global__ void detect_kernel(const int* __restrict__ t32) {
    if (threadIdx.x == 0) {
        int all_zero = 1;
        for (int i = 0; i < 256; i++) {
            int idx = 2 * (i * (NUM_TOKENS / 256)) + 1;
            if (t32[idx] != 0) { all_zero = 0; break; }
        }
        g_is64 = all_zero;
    }
    if (threadIdx.x < NUM_EXPERTS) g_counts[threadIdx.x] = 0;
}

__global__ void route_kernel(const int* __restrict__ t32) {
    int i = blockIdx.x * blockDim.x + threadIdx.x;
    if (i < NUM_TOKENS) {
        int v = g_is64 ? t32[2 * i] : t32[i];
        int e = v & 7;
        int p = atomicAdd(&g_counts[e], 1);
        g_lists[e][p] = i;
    }
}

// smem geometry (floats): A pitch 36 (128 rows), B pitch 72 (32 k-rows, 64 cols used)
#define APITCH 36
#define BPITCH 72
#define A_BYTES (128 * APITCH * 4)   /* 18432 */
#define B_BYTES (32 * BPITCH * 4)    /* 9216  */
#define G1_STAGE (A_BYTES + 2 * B_BYTES)  /* 36864 */
#define G2_STAGE (A_BYTES + B_BYTES)      /* 27648 */
#define G1_SMEM (512 + 2 * G1_STAGE)      /* 74240 */
#define G2_SMEM (512 + 2 * G2_STAGE)      /* 55808 */

// issue A tile (128 rows x 32 k) for chunk kc into stage q. rowsrc: per-token row base.
template <int STAGE>
__device__ __forceinline__ void issue_A(uint32_t sb, int q, const int* tokS,
                                        const float* src, int row_len, int kc, int tid) {
    int r = tid >> 1;
    int t = tokS[r];
    const float* arow = (t >= 0) ? (src + (size_t)t * row_len + kc * 32 + (tid & 1) * 4) : src;
    int ssz = (t >= 0) ? 16 : 0;
    uint32_t abase = sb + 512 + q * STAGE + r * (APITCH * 4) + (tid & 1) * 16;
#pragma unroll
    for (int q4 = 0; q4 < 4; q4++) cpa16(abase + q4 * 32, arow + q4 * 8, ssz);
}

// ---------------- GEMM1: X_e @ GU -> silu(gate)*up -> g_inter ----------------
__global__ __launch_bounds__(256) void gemm1_tc(const float* __restrict__ x,
                                                const float* __restrict__ gup) {
    extern __shared__ char smem[];
    const int e = blockIdx.z;
    const int count = g_counts[e];
    const int m0 = blockIdx.y * 128;
    if (m0 >= count) return;
    const int n0 = blockIdx.x * 64;

    int* tokS = (int*)smem;
    const uint32_t sb = smem_u32(smem);
    const int tid = threadIdx.x;
    const int wid = tid >> 5, lane = tid & 31;
    const int mw = wid >> 1, nw = wid & 1;
    const int g = lane >> 2, tq = lane & 3;

    if (tid < 128) tokS[tid] = (m0 + tid < count) ? g_lists[e][m0 + tid] : -1;
    __syncthreads();

    const float* Bx = gup + (size_t)e * HIDDEN * GU_COLS + n0;

    // B issue lambda-ish
    auto issue_B = [&](int kc, int q) {
#pragma unroll
        for (int h = 0; h < 2; h++) {
            int idx = tid + h * 256;
            int k = idx >> 4, n16 = (idx & 15) * 16;
            const float* gp = Bx + (size_t)(kc * 32 + k) * GU_COLS + (idx & 15) * 4;
            uint32_t base = sb + 512 + q * G1_STAGE + A_BYTES + k * (BPITCH * 4) + n16;
            cpa16(base, gp, 16);
            cpa16(base + B_BYTES, gp + INTER, 16);
        }
    };

    float accg[2][4][4] = {};
    float accu[2][4][4] = {};

    issue_A<G1_STAGE>(sb, 0, tokS, x, HIDDEN, 0, tid);
    issue_B(0, 0);
    cpa_commit();

    const int NK = HIDDEN / 32;
    int p = 0;
    for (int kc = 0; kc < NK; kc++) {
        if (kc + 1 < NK) {
            issue_A<G1_STAGE>(sb, p ^ 1, tokS, x, HIDDEN, kc + 1, tid);
            issue_B(kc + 1, p ^ 1);
            cpa_commit();
            cpa_wait1();
        } else {
            cpa_wait0();
        }
        __syncthreads();

        const float* As = (const float*)(smem + 512 + p * G1_STAGE);
        const float* Bg = As + 128 * APITCH;
        const float* Bu = Bg + 32 * BPITCH;

#pragma unroll
        for (int kk = 0; kk < 4; kk++) {
            uint32_t a[2][4];
#pragma unroll
            for (int mi = 0; mi < 2; mi++) {
                const float* ap = As + (mw * 32 + mi * 16 + g) * APITCH + kk * 8 + tq;
                a[mi][0] = f2tf(ap[0]);
                a[mi][1] = f2tf(ap[8 * APITCH]);
                a[mi][2] = f2tf(ap[4]);
                a[mi][3] = f2tf(ap[8 * APITCH + 4]);
            }
#pragma unroll
            for (int ni = 0; ni < 4; ni++) {
                const float* bp = Bg + (kk * 8 + tq) * BPITCH + nw * 32 + ni * 8 + g;
                uint32_t b0 = f2tf(bp[0]), b1 = f2tf(bp[4 * BPITCH]);
                mma8(accg[0][ni], a[0], b0, b1);
                mma8(accg[1][ni], a[1], b0, b1);
                const float* up = Bu + (kk * 8 + tq) * BPITCH + nw * 32 + ni * 8 + g;
                uint32_t u0 = f2tf(up[0]), u1 = f2tf(up[4 * BPITCH]);
                mma8(accu[0][ni], a[0], u0, u1);
                mma8(accu[1][ni], a[1], u0, u1);
            }
        }
        __syncthreads();
        p ^= 1;
    }

    // fused epilogue
#pragma unroll
    for (int mi = 0; mi < 2; mi++) {
        int r0 = mw * 32 + mi * 16 + g;
        int t0 = tokS[r0], t1 = tokS[r0 + 8];
#pragma unroll
        for (int ni = 0; ni < 4; ni++) {
            int col = n0 + nw * 32 + ni * 8 + 2 * tq;
            if (t0 >= 0) {
                float2 v = make_float2(silu(accg[mi][ni][0]) * accu[mi][ni][0],
                                       silu(accg[mi][ni][1]) * accu[mi][ni][1]);
                *(float2*)(g_inter + (size_t)t0 * INTER + col) = v;
            }
            if (t1 >= 0) {
                float2 v = make_float2(silu(accg[mi][ni][2]) * accu[mi][ni][2],
                                       silu(accg[mi][ni][3]) * accu[mi][ni][3]);
                *(float2*)(g_inter + (size_t)t1 * INTER + col) = v;
            }
        }
    }
}

// ---------------- GEMM2: g_inter @ down -> out ----------------
__global__ __launch_bounds__(256) void gemm2_tc(const float* __restrict__ down,
                                                float* __restrict__ out) {
    extern __shared__ char smem[];
    const int e = blockIdx.z;
    const int count = g_counts[e];
    const int m0 = blockIdx.y * 128;
    if (m0 >= count) return;
    const int n0 = blockIdx.x * 64;

    int* tokS = (int*)smem;
    const uint32_t sb = smem_u32(smem);
    const int tid = threadIdx.x;
    const int wid = tid >> 5, lane = tid & 31;
    const int mw = wid >> 1, nw = wid & 1;
    const int g = lane >> 2, tq = lane & 3;

    if (tid < 128) tokS[tid] = (m0 + tid < count) ? g_lists[e][m0 + tid] : -1;
    __syncthreads();

    const float* Bx = down + (size_t)e * INTER * HIDDEN + n0;

    auto issue_B = [&](int kc, int q) {
#pragma unroll
        for (int h = 0; h < 2; h++) {
            int idx = tid + h * 256;
            int k = idx >> 4, n16 = (idx & 15) * 16;
            const float* gp = Bx + (size_t)(kc * 32 + k) * HIDDEN + (idx & 15) * 4;
            uint32_t base = sb + 512 + q * G2_STAGE + A_BYTES + k * (BPITCH * 4) + n16;
            cpa16(base, gp, 16);
        }
    };

    float acc[2][4][4] = {};

    issue_A<G2_STAGE>(sb, 0, tokS, g_inter, INTER, 0, tid);
    issue_B(0, 0);
    cpa_commit();

    const int NK = INTER / 32;
    int p = 0;
    for (int kc = 0; kc < NK; kc++) {
        if (kc + 1 < NK) {
            issue_A<G2_STAGE>(sb, p ^ 1, tokS, g_inter, INTER, kc + 1, tid);
            issue_B(kc + 1, p ^ 1);
            cpa_commit();
            cpa_wait1();
        } else {
            cpa_wait0();
        }
        __syncthreads();

        const float* As = (const float*)(smem + 512 + p * G2_STAGE);
        const float* Bs = As + 128 * APITCH;

#pragma unroll
        for (int kk = 0; kk < 4; kk++) {
            uint32_t a[2][4];
#pragma unroll
            for (int mi = 0; mi < 2; mi++) {
                const float* ap = As + (mw * 32 + mi * 16 + g) * APITCH + kk * 8 + tq;
                a[mi][0] = f2tf(ap[0]);
                a[mi][1] = f2tf(ap[8 * APITCH]);
                a[mi][2] = f2tf(ap[4]);
                a[mi][3] = f2tf(ap[8 * APITCH + 4]);
            }
#pragma unroll
            for (int ni = 0; ni < 4; ni++) {
                const float* bp = Bs + (kk * 8 + tq) * BPITCH + nw * 32 + ni * 8 + g;
                uint32_t b0 = f2tf(bp[0]), b1 = f2tf(bp[4 * BPITCH]);
                mma8(acc[0][ni], a[0], b0, b1);
                mma8(acc[1][ni], a[1], b0, b1);
            }
        }
        __syncthreads();
        p ^= 1;
    }

#pragma unroll
    for (int mi = 0; mi < 2; mi++) {
        int r0 = mw * 32 + mi * 16 + g;
        int t0 = tokS[r0], t1 = tokS[r0 + 8];
#pragma unroll
        for (int ni = 0; ni < 4; ni++) {
            int col = n0 + nw * 32 + ni * 8 + 2 * tq;
            if (t0 >= 0)
                *(float2*)(out + (size_t)t0 * HIDDEN + col) =
                    make_float2(acc[mi][ni][0], acc[mi][ni][1]);
            if (t1 >= 0)
                *(float2*)(out + (size_t)t1 * HIDDEN + col) =
                    make_float2(acc[mi][ni][2], acc[mi][ni][3]);
        }
    }
}

// ---------------- launch ----------------
extern "C" void kernel_launch(void* const* d_in, const int* in_sizes, int n_in,
                              void* d_out, int out_size) {
    const float* x    = (const float*)d_in[0];
    const int*   tids = (const int*)d_in[1];
    const float* gup  = (const float*)d_in[2];
    const float* down = (const float*)d_in[3];
    float*       out  = (float*)d_out;

    static int attr_set = 0;
    if (!attr_set) {
        cudaFuncSetAttribute(gemm1_tc, cudaFuncAttributeMaxDynamicSharedMemorySize, G1_SMEM);
        cudaFuncSetAttribute(gemm2_tc, cudaFuncAttributeMaxDynamicSharedMemorySize, G2_SMEM);
        attr_set = 1;
    }

    detect_kernel<<<1, 32>>>(tids);
    route_kernel<<<NUM_TOKENS / 256, 256>>>(tids);

    gemm1_tc<<<dim3(INTER / 64, NUM_TOKENS / 128, NUM_EXPERTS), 256, G1_SMEM>>>(x, gup);
    gemm2_tc<<<dim3(HIDDEN / 64, NUM_TOKENS / 128, NUM_EXPERTS), 256, G2_SMEM>>>(down, out);
}

// round 5
// speedup vs baseline: 2.6774x; 1.0428x over previous
#include <cuda_runtime.h>
#include <cstdint>

#define NUM_TOKENS 8192
#define HIDDEN 4096
#define NUM_EXPERTS 8
#define INTER 2048
#define GU_COLS 4096
#define MAX_TILES 72

// ---------------- scratch ----------------
__device__ int   g_counts[NUM_EXPERTS];
__device__ int   g_lists[NUM_EXPERTS][NUM_TOKENS];
__device__ int   g_is64;
__device__ float g_inter[(size_t)NUM_TOKENS * INTER];

// ---------------- helpers ----------------
__device__ __forceinline__ uint32_t smem_u32(const void* p) {
    uint32_t a;
    asm("{ .reg .u64 t; cvta.to.shared.u64 t, %1; cvt.u32.u64 %0, t; }" : "=r"(a) : "l"(p));
    return a;
}
__device__ __forceinline__ uint32_t f2tf(float f) {
    uint32_t r;
    asm("cvt.rna.tf32.f32 %0, %1;" : "=r"(r) : "f"(f));
    return r;
}
__device__ __forceinline__ float4 cvt4(float4 v) {
    float4 r;
    r.x = __uint_as_float(f2tf(v.x));
    r.y = __uint_as_float(f2tf(v.y));
    r.z = __uint_as_float(f2tf(v.z));
    r.w = __uint_as_float(f2tf(v.w));
    return r;
}
__device__ __forceinline__ void mma8(float* d, const uint32_t* a, uint32_t b0, uint32_t b1) {
    asm volatile(
        "mma.sync.aligned.m16n8k8.row.col.f32.tf32.tf32.f32 "
        "{%0,%1,%2,%3},{%4,%5,%6,%7},{%8,%9},{%0,%1,%2,%3};"
        : "+f"(d[0]), "+f"(d[1]), "+f"(d[2]), "+f"(d[3])
        : "r"(a[0]), "r"(a[1]), "r"(a[2]), "r"(a[3]), "r"(b0), "r"(b1));
}
__device__ __forceinline__ void cpa16(uint32_t dst, const void* src, int srcsize) {
    asm volatile("cp.async.cg.shared.global [%0], [%1], 16, %2;" :: "r"(dst), "l"(src), "r"(srcsize));
}
__device__ __forceinline__ void cpa_commit() { asm volatile("cp.async.commit_group;" ::: "memory"); }
__device__ __forceinline__ void cpa_wait1()  { asm volatile("cp.async.wait_group 1;" ::: "memory"); }
__device__ __forceinline__ void cpa_wait0()  { asm volatile("cp.async.wait_group 0;" ::: "memory"); }

__device__ __forceinline__ float silu(float g) { return g / (1.0f + __expf(-g)); }

// map flat tile id -> (expert, m0). returns 0 if out of range.
__device__ __forceinline__ int find_tile(int t, int* e_out, int* m0_out, int* cnt_out) {
    int acc = 0;
#pragma unroll
    for (int e = 0; e < NUM_EXPERTS; e++) {
        int c = g_counts[e];
        int nt = (c + 127) >> 7;
        if (t < acc + nt) { *e_out = e; *m0_out = (t - acc) << 7; *cnt_out = c; return 1; }
        acc += nt;
    }
    return 0;
}

// ---------------- routing ----------------
__global__ void detect_kernel(const int* __restrict__ t32) {
    if (threadIdx.x == 0) {
        int all_zero = 1;
        for (int i = 0; i < 256; i++) {
            int idx = 2 * (i * (NUM_TOKENS / 256)) + 1;
            if (t32[idx] != 0) { all_zero = 0; break; }
        }
        g_is64 = all_zero;
    }
    if (threadIdx.x < NUM_EXPERTS) g_counts[threadIdx.x] = 0;
}

__global__ void route_kernel(const int* __restrict__ t32) {
    int i = blockIdx.x * blockDim.x + threadIdx.x;
    if (i < NUM_TOKENS) {
        int v = g_is64 ? t32[2 * i] : t32[i];
        int e = v & 7;
        int p = atomicAdd(&g_counts[e], 1);
        g_lists[e][p] = i;
    }
}

// smem geometry (floats)
#define APITCH 36
#define BPITCH 72      /* GEMM1 B: 64 cols */
#define BPITCH2 136    /* GEMM2 B: 128 cols */
#define A_BYTES  (128 * APITCH * 4)   /* 18432 */
#define B1_BYTES (32 * BPITCH * 4)    /* 9216  */
#define B2_BYTES (32 * BPITCH2 * 4)   /* 17408 */
#define G1_STAGE (A_BYTES + 2 * B1_BYTES)  /* 36864 */
#define G2_STAGE (A_BYTES + B2_BYTES)      /* 35840 */
#define G1_SMEM (512 + 2 * G1_STAGE)
#define G2_SMEM (512 + 2 * G2_STAGE)

template <int STAGE>
__device__ __forceinline__ void issue_A(uint32_t sb, int q, const int* tokS,
                                        const float* src, int row_len, int kc, int tid) {
    int r = tid >> 1;
    int t = tokS[r];
    const float* arow = (t >= 0) ? (src + (size_t)t * row_len + kc * 32 + (tid & 1) * 4) : src;
    int ssz = (t >= 0) ? 16 : 0;
    uint32_t abase = sb + 512 + q * STAGE + r * (APITCH * 4) + (tid & 1) * 16;
#pragma unroll
    for (int q4 = 0; q4 < 4; q4++) cpa16(abase + q4 * 32, arow + q4 * 8, ssz);
}

// ---------------- GEMM1: X_e @ GU -> silu(gate)*up -> g_inter (tf32-rounded) ----------------
__global__ __launch_bounds__(256, 2) void gemm1_tc(const float* __restrict__ x,
                                                   const float* __restrict__ gup) {
    extern __shared__ char smem[];
    int e, m0, count;
    if (!find_tile(blockIdx.y, &e, &m0, &count)) return;
    const int n0 = blockIdx.x * 64;

    int* tokS = (int*)smem;
    const uint32_t sb = smem_u32(smem);
    const int tid = threadIdx.x;
    const int wid = tid >> 5, lane = tid & 31;
    const int mw = wid >> 1, nw = wid & 1;
    const int g = lane >> 2, tq = lane & 3;

    if (tid < 128) tokS[tid] = (m0 + tid < count) ? g_lists[e][m0 + tid] : -1;
    __syncthreads();

    const float* Bx = gup + (size_t)e * HIDDEN * GU_COLS + n0;

    auto issue_B = [&](int kc, int q) {
#pragma unroll
        for (int h = 0; h < 2; h++) {
            int idx = tid + h * 256;
            int k = idx >> 4, n16 = (idx & 15) * 16;
            const float* gp = Bx + (size_t)(kc * 32 + k) * GU_COLS + (idx & 15) * 4;
            uint32_t base = sb + 512 + q * G1_STAGE + A_BYTES + k * (BPITCH * 4) + n16;
            cpa16(base, gp, 16);
            cpa16(base + B1_BYTES, gp + INTER, 16);
        }
    };

    float accg[2][4][4] = {};
    float accu[2][4][4] = {};

    issue_A<G1_STAGE>(sb, 0, tokS, x, HIDDEN, 0, tid);
    issue_B(0, 0);
    cpa_commit();

    const int NK = HIDDEN / 32;
    int p = 0;
    for (int kc = 0; kc < NK; kc++) {
        if (kc + 1 < NK) {
            issue_A<G1_STAGE>(sb, p ^ 1, tokS, x, HIDDEN, kc + 1, tid);
            issue_B(kc + 1, p ^ 1);
            cpa_commit();
            cpa_wait1();
        } else {
            cpa_wait0();
        }
        __syncthreads();

        float* As = (float*)(smem + 512 + p * G1_STAGE);
        float* Bg = As + 128 * APITCH;   // also covers Bu (contiguous tiles)

        // in-place fp32 -> tf32: A (128x32, pitch 36), Bg+Bu (2 x 32x64, pitch 72)
#pragma unroll
        for (int j = 0; j < 4; j++) {
            int c = tid + j * 256;                    // 1024 chunks
            float4* ap = (float4*)(As + (c >> 3) * APITCH + (c & 7) * 4);
            *ap = cvt4(*ap);
        }
#pragma unroll
        for (int j = 0; j < 4; j++) {
            int c = tid + j * 256;                    // 1024 chunks over 2 tiles
            int tile = c >> 9, row = (c >> 4) & 31, off = (c & 15) * 4;
            float4* bp4 = (float4*)(Bg + tile * (32 * BPITCH) + row * BPITCH + off);
            *bp4 = cvt4(*bp4);
        }
        __syncthreads();

        const float* Bu = Bg + 32 * BPITCH;
#pragma unroll
        for (int kk = 0; kk < 4; kk++) {
            uint32_t a[2][4];
#pragma unroll
            for (int mi = 0; mi < 2; mi++) {
                const float* ap = As + (mw * 32 + mi * 16 + g) * APITCH + kk * 8 + tq;
                a[mi][0] = __float_as_uint(ap[0]);
                a[mi][1] = __float_as_uint(ap[8 * APITCH]);
                a[mi][2] = __float_as_uint(ap[4]);
                a[mi][3] = __float_as_uint(ap[8 * APITCH + 4]);
            }
#pragma unroll
            for (int ni = 0; ni < 4; ni++) {
                const float* bp = Bg + (kk * 8 + tq) * BPITCH + nw * 32 + ni * 8 + g;
                uint32_t b0 = __float_as_uint(bp[0]), b1 = __float_as_uint(bp[4 * BPITCH]);
                mma8(accg[0][ni], a[0], b0, b1);
                mma8(accg[1][ni], a[1], b0, b1);
                const float* up = Bu + (kk * 8 + tq) * BPITCH + nw * 32 + ni * 8 + g;
                uint32_t u0 = __float_as_uint(up[0]), u1 = __float_as_uint(up[4 * BPITCH]);
                mma8(accu[0][ni], a[0], u0, u1);
                mma8(accu[1][ni], a[1], u0, u1);
            }
        }
        __syncthreads();
        p ^= 1;
    }

    // fused epilogue; store tf32-rounded so GEMM2 skips A conversion
#pragma unroll
    for (int mi = 0; mi < 2; mi++) {
        int r0 = mw * 32 + mi * 16 + g;
        int t0 = tokS[r0], t1 = tokS[r0 + 8];
#pragma unroll
        for (int ni = 0; ni < 4; ni++) {
            int col = n0 + nw * 32 + ni * 8 + 2 * tq;
            if (t0 >= 0) {
                float2 v;
                v.x = __uint_as_float(f2tf(silu(accg[mi][ni][0]) * accu[mi][ni][0]));
                v.y = __uint_as_float(f2tf(silu(accg[mi][ni][1]) * accu[mi][ni][1]));
                *(float2*)(g_inter + (size_t)t0 * INTER + col) = v;
            }
            if (t1 >= 0) {
                float2 v;
                v.x = __uint_as_float(f2tf(silu(accg[mi][ni][2]) * accu[mi][ni][2]));
                v.y = __uint_as_float(f2tf(silu(accg[mi][ni][3]) * accu[mi][ni][3]));
                *(float2*)(g_inter + (size_t)t1 * INTER + col) = v;
            }
        }
    }
}

// ---------------- GEMM2: g_inter @ down -> out  (BN=128) ----------------
__global__ __launch_bounds__(256, 2) void gemm2_tc(const float* __restrict__ down,
                                                   float* __restrict__ out) {
    extern __shared__ char smem[];
    int e, m0, count;
    if (!find_tile(blockIdx.y, &e, &m0, &count)) return;
    const int n0 = blockIdx.x * 128;

    int* tokS = (int*)smem;
    const uint32_t sb = smem_u32(smem);
    const int tid = threadIdx.x;
    const int wid = tid >> 5, lane = tid & 31;
    const int mw = wid >> 1, nw = wid & 1;
    const int g = lane >> 2, tq = lane & 3;

    if (tid < 128) tokS[tid] = (m0 + tid < count) ? g_lists[e][m0 + tid] : -1;
    __syncthreads();

    const float* Bx = down + (size_t)e * INTER * HIDDEN + n0;

    auto issue_B = [&](int kc, int q) {
#pragma unroll
        for (int h = 0; h < 4; h++) {
            int idx = tid + h * 256;                 // 1024 x 16B = 32 rows x 128 floats
            int k = idx >> 5, c4 = (idx & 31) * 4;
            const float* gp = Bx + (size_t)(kc * 32 + k) * HIDDEN + c4;
            uint32_t base = sb + 512 + q * G2_STAGE + A_BYTES + k * (BPITCH2 * 4) + c4 * 4;
            cpa16(base, gp, 16);
        }
    };

    float acc[2][8][4] = {};

    issue_A<G2_STAGE>(sb, 0, tokS, g_inter, INTER, 0, tid);
    issue_B(0, 0);
    cpa_commit();

    const int NK = INTER / 32;
    int p = 0;
    for (int kc = 0; kc < NK; kc++) {
        if (kc + 1 < NK) {
            issue_A<G2_STAGE>(sb, p ^ 1, tokS, g_inter, INTER, kc + 1, tid);
            issue_B(kc + 1, p ^ 1);
            cpa_commit();
            cpa_wait1();
        } else {
            cpa_wait0();
        }
        __syncthreads();

        float* As = (float*)(smem + 512 + p * G2_STAGE);
        float* Bs = As + 128 * APITCH;

        // A is already tf32-rounded (g_inter). Convert B only: 32 x 128, pitch 136.
#pragma unroll
        for (int j = 0; j < 4; j++) {
            int c = tid + j * 256;                   // 1024 chunks
            int row = c >> 5, off = (c & 31) * 4;
            float4* bp4 = (float4*)(Bs + row * BPITCH2 + off);
            *bp4 = cvt4(*bp4);
        }
        __syncthreads();

#pragma unroll
        for (int kk = 0; kk < 4; kk++) {
            uint32_t a[2][4];
#pragma unroll
            for (int mi = 0; mi < 2; mi++) {
                const float* ap = As + (mw * 32 + mi * 16 + g) * APITCH + kk * 8 + tq;
                a[mi][0] = __float_as_uint(ap[0]);
                a[mi][1] = __float_as_uint(ap[8 * APITCH]);
                a[mi][2] = __float_as_uint(ap[4]);
                a[mi][3] = __float_as_uint(ap[8 * APITCH + 4]);
            }
#pragma unroll
            for (int ni = 0; ni < 8; ni++) {
                const float* bp = Bs + (kk * 8 + tq) * BPITCH2 + nw * 64 + ni * 8 + g;
                uint32_t b0 = __float_as_uint(bp[0]), b1 = __float_as_uint(bp[4 * BPITCH2]);
                mma8(acc[0][ni], a[0], b0, b1);
                mma8(acc[1][ni], a[1], b0, b1);
            }
        }
        __syncthreads();
        p ^= 1;
    }

#pragma unroll
    for (int mi = 0; mi < 2; mi++) {
        int r0 = mw * 32 + mi * 16 + g;
        int t0 = tokS[r0], t1 = tokS[r0 + 8];
#pragma unroll
        for (int ni = 0; ni < 8; ni++) {
            int col = n0 + nw * 64 + ni * 8 + 2 * tq;
            if (t0 >= 0)
                *(float2*)(out + (size_t)t0 * HIDDEN + col) =
                    make_float2(acc[mi][ni][0], acc[mi][ni][1]);
            if (t1 >= 0)
                *(float2*)(out + (size_t)t1 * HIDDEN + col) =
                    make_float2(acc[mi][ni][2], acc[mi][ni][3]);
        }
    }
}

// ---------------- launch ----------------
extern "C" void kernel_launch(void* const* d_in, const int* in_sizes, int n_in,
                              void* d_out, int out_size) {
    const float* x    = (const float*)d_in[0];
    const int*   tids = (const int*)d_in[1];
    const float* gup  = (const float*)d_in[2];
    const float* down = (const float*)d_in[3];
    float*       out  = (float*)d_out;

    cudaFuncSetAttribute(gemm1_tc, cudaFuncAttributeMaxDynamicSharedMemorySize, G1_SMEM);
    cudaFuncSetAttribute(gemm2_tc, cudaFuncAttributeMaxDynamicSharedMemorySize, G2_SMEM);

    detect_kernel<<<1, 32>>>(tids);
    route_kernel<<<NUM_TOKENS / 256, 256>>>(tids);

    gemm1_tc<<<dim3(INTER / 64, MAX_TILES), 256, G1_SMEM>>>(x, gup);
    gemm2_tc<<<dim3(HIDDEN / 128, MAX_TILES), 256, G2_SMEM>>>(down, out);
}

// round 6
// speedup vs baseline: 2.8560x; 1.0667x over previous
#include <cuda_runtime.h>
#include <cstdint>

#define NUM_TOKENS 8192
#define HIDDEN 4096
#define NUM_EXPERTS 8
#define INTER 2048
#define GU_COLS 4096
#define MAX_TILES 72

// ---------------- scratch ----------------
__device__ int   g_counts[NUM_EXPERTS];
__device__ int   g_lists[NUM_EXPERTS][NUM_TOKENS];
__device__ int   g_is64;
__device__ float g_inter[(size_t)NUM_TOKENS * INTER];

// ---------------- helpers ----------------
__device__ __forceinline__ uint32_t smem_u32(const void* p) {
    uint32_t a;
    asm("{ .reg .u64 t; cvta.to.shared.u64 t, %1; cvt.u32.u64 %0, t; }" : "=r"(a) : "l"(p));
    return a;
}
__device__ __forceinline__ uint32_t f2tf(float f) {
    uint32_t r;
    asm("cvt.rna.tf32.f32 %0, %1;" : "=r"(r) : "f"(f));
    return r;
}
__device__ __forceinline__ void mma8(float* d, const uint32_t* a, uint32_t b0, uint32_t b1) {
    asm volatile(
        "mma.sync.aligned.m16n8k8.row.col.f32.tf32.tf32.f32 "
        "{%0,%1,%2,%3},{%4,%5,%6,%7},{%8,%9},{%0,%1,%2,%3};"
        : "+f"(d[0]), "+f"(d[1]), "+f"(d[2]), "+f"(d[3])
        : "r"(a[0]), "r"(a[1]), "r"(a[2]), "r"(a[3]), "r"(b0), "r"(b1));
}
__device__ __forceinline__ void cpa16(uint32_t dst, const void* src, int srcsize) {
    asm volatile("cp.async.cg.shared.global [%0], [%1], 16, %2;" :: "r"(dst), "l"(src), "r"(srcsize));
}
__device__ __forceinline__ void cpa_commit() { asm volatile("cp.async.commit_group;" ::: "memory"); }
__device__ __forceinline__ void cpa_wait1()  { asm volatile("cp.async.wait_group 1;" ::: "memory"); }
__device__ __forceinline__ void cpa_wait0()  { asm volatile("cp.async.wait_group 0;" ::: "memory"); }

__device__ __forceinline__ float silu(float g) { return g / (1.0f + __expf(-g)); }

__device__ __forceinline__ int find_tile(int t, int* e_out, int* m0_out, int* cnt_out) {
    int acc = 0;
#pragma unroll
    for (int e = 0; e < NUM_EXPERTS; e++) {
        int c = g_counts[e];
        int nt = (c + 127) >> 7;
        if (t < acc + nt) { *e_out = e; *m0_out = (t - acc) << 7; *cnt_out = c; return 1; }
        acc += nt;
    }
    return 0;
}

// ---------------- routing ----------------
__global__ void detect_kernel(const int* __restrict__ t32) {
    if (threadIdx.x == 0) {
        int all_zero = 1;
        for (int i = 0; i < 256; i++) {
            int idx = 2 * (i * (NUM_TOKENS / 256)) + 1;
            if (t32[idx] != 0) { all_zero = 0; break; }
        }
        g_is64 = all_zero;
    }
    if (threadIdx.x < NUM_EXPERTS) g_counts[threadIdx.x] = 0;
}

__global__ void route_kernel(const int* __restrict__ t32) {
    int i = blockIdx.x * blockDim.x + threadIdx.x;
    if (i < NUM_TOKENS) {
        int v = g_is64 ? t32[2 * i] : t32[i];
        int e = v & 7;
        int p = atomicAdd(&g_counts[e], 1);
        g_lists[e][p] = i;
    }
}

// smem geometry (floats)
#define APITCH 36
#define BPITCH 72      /* GEMM1 B: 64 cols */
#define BPITCH2 136    /* GEMM2 B: 128 cols */
#define A_BYTES  (128 * APITCH * 4)   /* 18432 */
#define B1_BYTES (32 * BPITCH * 4)    /* 9216  */
#define B2_BYTES (32 * BPITCH2 * 4)   /* 17408 */
#define G1_STAGE (A_BYTES + 2 * B1_BYTES)  /* 36864 */
#define G2_STAGE (A_BYTES + B2_BYTES)      /* 35840 */
#define NSTAGE 3
#define G1_SMEM (512 + NSTAGE * G1_STAGE)  /* 111104 */
#define G2_SMEM (512 + NSTAGE * G2_STAGE)  /* 108032 */

template <int STAGE>
__device__ __forceinline__ void issue_A(uint32_t sb, int q, const int* tokS,
                                        const float* src, int row_len, int kc, int tid) {
    int r = tid >> 1;
    int t = tokS[r];
    const float* arow = (t >= 0) ? (src + (size_t)t * row_len + kc * 32 + (tid & 1) * 4) : src;
    int ssz = (t >= 0) ? 16 : 0;
    uint32_t abase = sb + 512 + q * STAGE + r * (APITCH * 4) + (tid & 1) * 16;
#pragma unroll
    for (int q4 = 0; q4 < 4; q4++) cpa16(abase + q4 * 32, arow + q4 * 8, ssz);
}

// ---------------- GEMM1: X_e @ GU -> silu(gate)*up -> g_inter (tf32-rounded) ----------------
__global__ __launch_bounds__(256, 2) void gemm1_tc(const float* __restrict__ x,
                                                   const float* __restrict__ gup) {
    extern __shared__ char smem[];
    int e, m0, count;
    if (!find_tile(blockIdx.y, &e, &m0, &count)) return;
    const int n0 = blockIdx.x * 64;

    int* tokS = (int*)smem;
    const uint32_t sb = smem_u32(smem);
    const int tid = threadIdx.x;
    const int wid = tid >> 5, lane = tid & 31;
    const int mw = wid >> 1, nw = wid & 1;
    const int g = lane >> 2, tq = lane & 3;

    if (tid < 128) tokS[tid] = (m0 + tid < count) ? g_lists[e][m0 + tid] : -1;
    __syncthreads();

    const float* Bx = gup + (size_t)e * HIDDEN * GU_COLS + n0;

    auto issue_B = [&](int kc, int q) {
#pragma unroll
        for (int h = 0; h < 2; h++) {
            int idx = tid + h * 256;
            int k = idx >> 4, n16 = (idx & 15) * 16;
            const float* gp = Bx + (size_t)(kc * 32 + k) * GU_COLS + (idx & 15) * 4;
            uint32_t base = sb + 512 + q * G1_STAGE + A_BYTES + k * (BPITCH * 4) + n16;
            cpa16(base, gp, 16);
            cpa16(base + B1_BYTES, gp + INTER, 16);
        }
    };

    float accg[2][4][4] = {};
    float accu[2][4][4] = {};

    issue_A<G1_STAGE>(sb, 0, tokS, x, HIDDEN, 0, tid);
    issue_B(0, 0);
    cpa_commit();
    issue_A<G1_STAGE>(sb, 1, tokS, x, HIDDEN, 1, tid);
    issue_B(1, 1);
    cpa_commit();

    const int NK = HIDDEN / 32;
    for (int kc = 0; kc < NK; kc++) {
        const int slot = kc % NSTAGE;
        if (kc + 1 < NK) cpa_wait1(); else cpa_wait0();
        __syncthreads();
        if (kc + 2 < NK) {
            const int ns = (kc + 2) % NSTAGE;
            issue_A<G1_STAGE>(sb, ns, tokS, x, HIDDEN, kc + 2, tid);
            issue_B(kc + 2, ns);
            cpa_commit();
        }

        const float* As = (const float*)(smem + 512 + slot * G1_STAGE);
        const float* Bg = As + 128 * APITCH;
        const float* Bu = Bg + 32 * BPITCH;

#pragma unroll
        for (int kk = 0; kk < 4; kk++) {
            uint32_t a[2][4];
#pragma unroll
            for (int mi = 0; mi < 2; mi++) {
                const float* ap = As + (mw * 32 + mi * 16 + g) * APITCH + kk * 8 + tq;
                a[mi][0] = f2tf(ap[0]);
                a[mi][1] = f2tf(ap[8 * APITCH]);
                a[mi][2] = f2tf(ap[4]);
                a[mi][3] = f2tf(ap[8 * APITCH + 4]);
            }
#pragma unroll
            for (int ni = 0; ni < 4; ni++) {
                const float* bp = Bg + (kk * 8 + tq) * BPITCH + nw * 32 + ni * 8 + g;
                uint32_t b0 = f2tf(bp[0]), b1 = f2tf(bp[4 * BPITCH]);
                mma8(accg[0][ni], a[0], b0, b1);
                mma8(accg[1][ni], a[1], b0, b1);
                const float* up = Bu + (kk * 8 + tq) * BPITCH + nw * 32 + ni * 8 + g;
                uint32_t u0 = f2tf(up[0]), u1 = f2tf(up[4 * BPITCH]);
                mma8(accu[0][ni], a[0], u0, u1);
                mma8(accu[1][ni], a[1], u0, u1);
            }
        }
    }

    // fused epilogue; store tf32-rounded so GEMM2 skips A conversion
#pragma unroll
    for (int mi = 0; mi < 2; mi++) {
        int r0 = mw * 32 + mi * 16 + g;
        int t0 = tokS[r0], t1 = tokS[r0 + 8];
#pragma unroll
        for (int ni = 0; ni < 4; ni++) {
            int col = n0 + nw * 32 + ni * 8 + 2 * tq;
            if (t0 >= 0) {
                float2 v;
                v.x = __uint_as_float(f2tf(silu(accg[mi][ni][0]) * accu[mi][ni][0]));
                v.y = __uint_as_float(f2tf(silu(accg[mi][ni][1]) * accu[mi][ni][1]));
                *(float2*)(g_inter + (size_t)t0 * INTER + col) = v;
            }
            if (t1 >= 0) {
                float2 v;
                v.x = __uint_as_float(f2tf(silu(accg[mi][ni][2]) * accu[mi][ni][2]));
                v.y = __uint_as_float(f2tf(silu(accg[mi][ni][3]) * accu[mi][ni][3]));
                *(float2*)(g_inter + (size_t)t1 * INTER + col) = v;
            }
        }
    }
}

// ---------------- GEMM2: g_inter @ down -> out  (BN=128) ----------------
__global__ __launch_bounds__(256, 2) void gemm2_tc(const float* __restrict__ down,
                                                   float* __restrict__ out) {
    extern __shared__ char smem[];
    int e, m0, count;
    if (!find_tile(blockIdx.y, &e, &m0, &count)) return;
    const int n0 = blockIdx.x * 128;

    int* tokS = (int*)smem;
    const uint32_t sb = smem_u32(smem);
    const int tid = threadIdx.x;
    const int wid = tid >> 5, lane = tid & 31;
    const int mw = wid >> 1, nw = wid & 1;
    const int g = lane >> 2, tq = lane & 3;

    if (tid < 128) tokS[tid] = (m0 + tid < count) ? g_lists[e][m0 + tid] : -1;
    __syncthreads();

    const float* Bx = down + (size_t)e * INTER * HIDDEN + n0;

    auto issue_B = [&](int kc, int q) {
#pragma unroll
        for (int h = 0; h < 4; h++) {
            int idx = tid + h * 256;                 // 1024 x 16B = 32 rows x 128 floats
            int k = idx >> 5, c4 = (idx & 31) * 4;
            const float* gp = Bx + (size_t)(kc * 32 + k) * HIDDEN + c4;
            uint32_t base = sb + 512 + q * G2_STAGE + A_BYTES + k * (BPITCH2 * 4) + c4 * 4;
            cpa16(base, gp, 16);
        }
    };

    float acc[2][8][4] = {};

    issue_A<G2_STAGE>(sb, 0, tokS, g_inter, INTER, 0, tid);
    issue_B(0, 0);
    cpa_commit();
    issue_A<G2_STAGE>(sb, 1, tokS, g_inter, INTER, 1, tid);
    issue_B(1, 1);
    cpa_commit();

    const int NK = INTER / 32;
    for (int kc = 0; kc < NK; kc++) {
        const int slot = kc % NSTAGE;
        if (kc + 1 < NK) cpa_wait1(); else cpa_wait0();
        __syncthreads();
        if (kc + 2 < NK) {
            const int ns = (kc + 2) % NSTAGE;
            issue_A<G2_STAGE>(sb, ns, tokS, g_inter, INTER, kc + 2, tid);
            issue_B(kc + 2, ns);
            cpa_commit();
        }

        const float* As = (const float*)(smem + 512 + slot * G2_STAGE);
        const float* Bs = As + 128 * APITCH;

#pragma unroll
        for (int kk = 0; kk < 4; kk++) {
            uint32_t a[2][4];
#pragma unroll
            for (int mi = 0; mi < 2; mi++) {
                const float* ap = As + (mw * 32 + mi * 16 + g) * APITCH + kk * 8 + tq;
                // A already tf32-rounded (g_inter): reinterpret only
                a[mi][0] = __float_as_uint(ap[0]);
                a[mi][1] = __float_as_uint(ap[8 * APITCH]);
                a[mi][2] = __float_as_uint(ap[4]);
                a[mi][3] = __float_as_uint(ap[8 * APITCH + 4]);
            }
#pragma unroll
            for (int ni = 0; ni < 8; ni++) {
                const float* bp = Bs + (kk * 8 + tq) * BPITCH2 + nw * 64 + ni * 8 + g;
                uint32_t b0 = f2tf(bp[0]), b1 = f2tf(bp[4 * BPITCH2]);
                mma8(acc[0][ni], a[0], b0, b1);
                mma8(acc[1][ni], a[1], b0, b1);
            }
        }
    }

#pragma unroll
    for (int mi = 0; mi < 2; mi++) {
        int r0 = mw * 32 + mi * 16 + g;
        int t0 = tokS[r0], t1 = tokS[r0 + 8];
#pragma unroll
        for (int ni = 0; ni < 8; ni++) {
            int col = n0 + nw * 64 + ni * 8 + 2 * tq;
            if (t0 >= 0)
                *(float2*)(out + (size_t)t0 * HIDDEN + col) =
                    make_float2(acc[mi][ni][0], acc[mi][ni][1]);
            if (t1 >= 0)
                *(float2*)(out + (size_t)t1 * HIDDEN + col) =
                    make_float2(acc[mi][ni][2], acc[mi][ni][3]);
        }
    }
}

// ---------------- launch ----------------
extern "C" void kernel_launch(void* const* d_in, const int* in_sizes, int n_in,
                              void* d_out, int out_size) {
    const float* x    = (const float*)d_in[0];
    const int*   tids = (const int*)d_in[1];
    const float* gup  = (const float*)d_in[2];
    const float* down = (const float*)d_in[3];
    float*       out  = (float*)d_out;

    cudaFuncSetAttribute(gemm1_tc, cudaFuncAttributeMaxDynamicSharedMemorySize, G1_SMEM);
    cudaFuncSetAttribute(gemm2_tc, cudaFuncAttributeMaxDynamicSharedMemorySize, G2_SMEM);

    detect_kernel<<<1, 32>>>(tids);
    route_kernel<<<NUM_TOKENS / 256, 256>>>(tids);

    gemm1_tc<<<dim3(INTER / 64, MAX_TILES), 256, G1_SMEM>>>(x, gup);
    gemm2_tc<<<dim3(HIDDEN / 128, MAX_TILES), 256, G2_SMEM>>>(down, out);
}

// round 7
// speedup vs baseline: 3.8093x; 1.3338x over previous
#include <cuda_runtime.h>
#include <cstdint>

#define NUM_TOKENS 8192
#define HIDDEN 4096
#define NUM_EXPERTS 8
#define INTER 2048
#define GU_COLS 4096
#define MAX_TILES 72
#define NSTAGE 3

// ---------------- scratch ----------------
__device__ int g_counts[NUM_EXPERTS];
__device__ int g_lists[NUM_EXPERTS][NUM_TOKENS];
__device__ int g_is64;
// fragment-packed activations: [tile][kfrag][mfrag 8][128 floats]
__device__ float g_xpack[(size_t)MAX_TILES * (HIDDEN / 8) * 8 * 128];   // 151 MB
__device__ float g_interp[(size_t)MAX_TILES * (INTER / 8) * 8 * 128];   // 75.5 MB

// ---------------- helpers ----------------
__device__ __forceinline__ uint32_t smem_u32(const void* p) {
    uint32_t a;
    asm("{ .reg .u64 t; cvta.to.shared.u64 t, %1; cvt.u32.u64 %0, t; }" : "=r"(a) : "l"(p));
    return a;
}
__device__ __forceinline__ uint32_t f2tf(float f) {
    uint32_t r;
    asm("cvt.rna.tf32.f32 %0, %1;" : "=r"(r) : "f"(f));
    return r;
}
__device__ __forceinline__ float4 cvt4(float4 v) {
    float4 r;
    r.x = __uint_as_float(f2tf(v.x));
    r.y = __uint_as_float(f2tf(v.y));
    r.z = __uint_as_float(f2tf(v.z));
    r.w = __uint_as_float(f2tf(v.w));
    return r;
}
__device__ __forceinline__ void mma8(float* d, const uint32_t* a, uint32_t b0, uint32_t b1) {
    asm volatile(
        "mma.sync.aligned.m16n8k8.row.col.f32.tf32.tf32.f32 "
        "{%0,%1,%2,%3},{%4,%5,%6,%7},{%8,%9},{%0,%1,%2,%3};"
        : "+f"(d[0]), "+f"(d[1]), "+f"(d[2]), "+f"(d[3])
        : "r"(a[0]), "r"(a[1]), "r"(a[2]), "r"(a[3]), "r"(b0), "r"(b1));
}
__device__ __forceinline__ void cpa16(uint32_t dst, const void* src, int srcsize) {
    asm volatile("cp.async.cg.shared.global [%0], [%1], 16, %2;" :: "r"(dst), "l"(src), "r"(srcsize));
}
__device__ __forceinline__ void cpa_commit() { asm volatile("cp.async.commit_group;" ::: "memory"); }
__device__ __forceinline__ void cpa_wait1()  { asm volatile("cp.async.wait_group 1;" ::: "memory"); }
__device__ __forceinline__ void cpa_wait0()  { asm volatile("cp.async.wait_group 0;" ::: "memory"); }

__device__ __forceinline__ float silu(float g) { return g / (1.0f + __expf(-g)); }

__device__ __forceinline__ int find_tile(int t, int* e_out, int* m0_out, int* cnt_out) {
    int acc = 0;
#pragma unroll
    for (int e = 0; e < NUM_EXPERTS; e++) {
        int c = g_counts[e];
        int nt = (c + 127) >> 7;
        if (t < acc + nt) { *e_out = e; *m0_out = (t - acc) << 7; *cnt_out = c; return 1; }
        acc += nt;
    }
    return 0;
}

// ---------------- routing ----------------
__global__ void detect_kernel(const int* __restrict__ t32) {
    if (threadIdx.x == 0) {
        int all_zero = 1;
        for (int i = 0; i < 256; i++) {
            int idx = 2 * (i * (NUM_TOKENS / 256)) + 1;
            if (t32[idx] != 0) { all_zero = 0; break; }
        }
        g_is64 = all_zero;
    }
    if (threadIdx.x < NUM_EXPERTS) g_counts[threadIdx.x] = 0;
}

__global__ void route_kernel(const int* __restrict__ t32) {
    int i = blockIdx.x * blockDim.x + threadIdx.x;
    if (i < NUM_TOKENS) {
        int v = g_is64 ? t32[2 * i] : t32[i];
        int e = v & 7;
        int p = atomicAdd(&g_counts[e], 1);
        g_lists[e][p] = i;
    }
}

// ---------------- pack_x: gather routed tokens into tf32 fragment layout ----------------
#define PX_PITCH 132
#define PX_SMEM (128 * PX_PITCH * 4 + 512)
__global__ __launch_bounds__(256) void pack_x_kernel(const float* __restrict__ x) {
    extern __shared__ char smem[];
    int e, m0, count;
    if (!find_tile(blockIdx.y, &e, &m0, &count)) return;
    const int kb = blockIdx.x;           // 128-col block of K
    const int tid = threadIdx.x;
    int* tokS = (int*)smem;
    float* tile = (float*)(smem + 512);
    if (tid < 128) tokS[tid] = (m0 + tid < count) ? g_lists[e][m0 + tid] : -1;
    __syncthreads();
#pragma unroll
    for (int j = 0; j < 16; j++) {
        int idx = tid + j * 256;
        int r = idx >> 5, c4 = (idx & 31) * 4;
        int t = tokS[r];
        float4 v = make_float4(0.f, 0.f, 0.f, 0.f);
        if (t >= 0) v = *(const float4*)(x + (size_t)t * HIDDEN + kb * 128 + c4);
        *(float4*)(tile + r * PX_PITCH + c4) = cvt4(v);   // pre-round to tf32
    }
    __syncthreads();
    const int lane = tid & 31, w = tid >> 5;
    const int g = lane >> 2, tq = lane & 3;
#pragma unroll
    for (int i = 0; i < 16; i++) {
        int f = w * 16 + i;
        int mf = f & 7, kfl = f >> 3;
        const float* src = tile + (mf * 16 + g) * PX_PITCH + kfl * 8 + tq;
        float4 o;
        o.x = src[0];
        o.y = src[8 * PX_PITCH];
        o.z = src[4];
        o.w = src[8 * PX_PITCH + 4];
        size_t off = (((size_t)blockIdx.y * (HIDDEN / 8) + kb * 16 + kfl) * 8 + mf) * 128 + lane * 4;
        *(float4*)(g_xpack + off) = o;
    }
}

// smem geometry
#define A_BYTES 16384                 /* packed A: 4 kfrag x 8 mfrag x 512B */
#define BPITCH 72                     /* GEMM1 B: 64 cols */
#define BPITCH2 136                   /* GEMM2 B: 128 cols */
#define B1_BYTES (32 * BPITCH * 4)    /* 9216  */
#define B2_BYTES (32 * BPITCH2 * 4)   /* 17408 */
#define G1_STAGE (A_BYTES + 2 * B1_BYTES)  /* 34816 */
#define G2_STAGE (A_BYTES + B2_BYTES)      /* 33792 */
#define G1_SMEM (512 + NSTAGE * G1_STAGE)  /* 104960 */
#define G2_SMEM (512 + NSTAGE * G2_STAGE)  /* 101888 */

// contiguous 16KB packed-A copy for chunk kc (4 kfrags)
__device__ __forceinline__ void issue_Apk(uint32_t sb, int soff, const float* apack,
                                          int kc, int tid) {
    const float* src = apack + (size_t)kc * 4096;    // 4 kfrag * 8 mfrag * 128 floats
#pragma unroll
    for (int j = 0; j < 4; j++) {
        int idx = tid + j * 256;
        cpa16(sb + 512 + soff + idx * 16, src + idx * 4, 16);
    }
}

// ---------------- GEMM1: Xpack @ GU -> silu(gate)*up -> g_interp (packed) ----------------
__global__ __launch_bounds__(256, 2) void gemm1_tc(const float* __restrict__ gup) {
    extern __shared__ char smem[];
    int e, m0, count;
    if (!find_tile(blockIdx.y, &e, &m0, &count)) return;
    const int n0 = blockIdx.x * 64;
    const int t_id = blockIdx.y;

    int* tokS = (int*)smem;
    const uint32_t sb = smem_u32(smem);
    const int tid = threadIdx.x;
    const int wid = tid >> 5, lane = tid & 31;
    const int mw = wid >> 1, nw = wid & 1;
    const int g = lane >> 2, tq = lane & 3;

    if (tid < 128) tokS[tid] = (m0 + tid < count) ? g_lists[e][m0 + tid] : -1;
    __syncthreads();

    const float* apack = g_xpack + (size_t)t_id * (HIDDEN / 8) * 1024;
    const float* Bx = gup + (size_t)e * HIDDEN * GU_COLS + n0;

    auto issue_B = [&](int kc, int soff) {
#pragma unroll
        for (int h = 0; h < 2; h++) {
            int idx = tid + h * 256;
            int k = idx >> 4, n16 = (idx & 15) * 16;
            const float* gp = Bx + (size_t)(kc * 32 + k) * GU_COLS + (idx & 15) * 4;
            uint32_t base = sb + 512 + soff + A_BYTES + k * (BPITCH * 4) + n16;
            cpa16(base, gp, 16);
            cpa16(base + B1_BYTES, gp + INTER, 16);
        }
    };

    float accg[2][4][4] = {};
    float accu[2][4][4] = {};

    issue_Apk(sb, 0, apack, 0, tid);
    issue_B(0, 0);
    cpa_commit();
    issue_Apk(sb, G1_STAGE, apack, 1, tid);
    issue_B(1, G1_STAGE);
    cpa_commit();

    const int NK = HIDDEN / 32;
    int soff_c = 0, soff_p = 2 * G1_STAGE;
    for (int kc = 0; kc < NK; kc++) {
        if (kc + 1 < NK) cpa_wait1(); else cpa_wait0();
        __syncthreads();
        if (kc + 2 < NK) {
            issue_Apk(sb, soff_p, apack, kc + 2, tid);
            issue_B(kc + 2, soff_p);
            cpa_commit();
        }

        const float* As = (const float*)(smem + 512 + soff_c);
        const float* Bg = As + A_BYTES / 4;
        const float* Bu = Bg + 32 * BPITCH;

#pragma unroll
        for (int kk = 0; kk < 4; kk++) {
            uint32_t a[2][4];
#pragma unroll
            for (int mi = 0; mi < 2; mi++) {
                const float4 av = *(const float4*)(As + ((kk * 8 + mw * 2 + mi) * 128) + lane * 4);
                a[mi][0] = __float_as_uint(av.x);
                a[mi][1] = __float_as_uint(av.y);
                a[mi][2] = __float_as_uint(av.z);
                a[mi][3] = __float_as_uint(av.w);
            }
#pragma unroll
            for (int ni = 0; ni < 4; ni++) {
                const float* bp = Bg + (kk * 8 + tq) * BPITCH + nw * 32 + ni * 8 + g;
                uint32_t b0 = f2tf(bp[0]), b1 = f2tf(bp[4 * BPITCH]);
                mma8(accg[0][ni], a[0], b0, b1);
                mma8(accg[1][ni], a[1], b0, b1);
                const float* up = Bu + (kk * 8 + tq) * BPITCH + nw * 32 + ni * 8 + g;
                uint32_t u0 = f2tf(up[0]), u1 = f2tf(up[4 * BPITCH]);
                mma8(accu[0][ni], a[0], u0, u1);
                mma8(accu[1][ni], a[1], u0, u1);
            }
        }
        soff_c += G1_STAGE; if (soff_c == NSTAGE * G1_STAGE) soff_c = 0;
        soff_p += G1_STAGE; if (soff_p == NSTAGE * G1_STAGE) soff_p = 0;
    }

    // fused epilogue -> fragment-packed g_interp (tf32-rounded)
#pragma unroll
    for (int mi = 0; mi < 2; mi++) {
        int mf = mw * 2 + mi;
        int r0 = mw * 32 + mi * 16 + g;
        int t0 = tokS[r0], t1 = tokS[r0 + 8];
#pragma unroll
        for (int ni = 0; ni < 4; ni++) {
            int c = nw * 32 + ni * 8 + 2 * tq;
            int kf = (n0 + c) >> 3;
            int hc2 = ((c >> 2) & 1) * 2;
            int tq0 = c & 3;
            float* base = g_interp + (((size_t)t_id * (INTER / 8) + kf) * 8 + mf) * 128;
            if (t0 >= 0) {
                base[(g * 4 + tq0) * 4 + hc2] =
                    __uint_as_float(f2tf(silu(accg[mi][ni][0]) * accu[mi][ni][0]));
                base[(g * 4 + tq0 + 1) * 4 + hc2] =
                    __uint_as_float(f2tf(silu(accg[mi][ni][1]) * accu[mi][ni][1]));
            }
            if (t1 >= 0) {
                base[(g * 4 + tq0) * 4 + 1 + hc2] =
                    __uint_as_float(f2tf(silu(accg[mi][ni][2]) * accu[mi][ni][2]));
                base[(g * 4 + tq0 + 1) * 4 + 1 + hc2] =
                    __uint_as_float(f2tf(silu(accg[mi][ni][3]) * accu[mi][ni][3]));
            }
        }
    }
}

// ---------------- GEMM2: g_interp @ down -> out  (BN=128) ----------------
__global__ __launch_bounds__(256, 2) void gemm2_tc(const float* __restrict__ down,
                                                   float* __restrict__ out) {
    extern __shared__ char smem[];
    int e, m0, count;
    if (!find_tile(blockIdx.y, &e, &m0, &count)) return;
    const int n0 = blockIdx.x * 128;
    const int t_id = blockIdx.y;

    int* tokS = (int*)smem;
    const uint32_t sb = smem_u32(smem);
    const int tid = threadIdx.x;
    const int wid = tid >> 5, lane = tid & 31;
    const int mw = wid >> 1, nw = wid & 1;
    const int g = lane >> 2, tq = lane & 3;

    if (tid < 128) tokS[tid] = (m0 + tid < count) ? g_lists[e][m0 + tid] : -1;
    __syncthreads();

    const float* apack = g_interp + (size_t)t_id * (INTER / 8) * 1024;
    const float* Bx = down + (size_t)e * INTER * HIDDEN + n0;

    auto issue_B = [&](int kc, int soff) {
#pragma unroll
        for (int h = 0; h < 4; h++) {
            int idx = tid + h * 256;
            int k = idx >> 5, c4 = (idx & 31) * 4;
            const float* gp = Bx + (size_t)(kc * 32 + k) * HIDDEN + c4;
            uint32_t base = sb + 512 + soff + A_BYTES + k * (BPITCH2 * 4) + c4 * 4;
            cpa16(base, gp, 16);
        }
    };

    float acc[2][8][4] = {};

    issue_Apk(sb, 0, apack, 0, tid);
    issue_B(0, 0);
    cpa_commit();
    issue_Apk(sb, G2_STAGE, apack, 1, tid);
    issue_B(1, G2_STAGE);
    cpa_commit();

    const int NK = INTER / 32;
    int soff_c = 0, soff_p = 2 * G2_STAGE;
    for (int kc = 0; kc < NK; kc++) {
        if (kc + 1 < NK) cpa_wait1(); else cpa_wait0();
        __syncthreads();
        if (kc + 2 < NK) {
            issue_Apk(sb, soff_p, apack, kc + 2, tid);
            issue_B(kc + 2, soff_p);
            cpa_commit();
        }

        const float* As = (const float*)(smem + 512 + soff_c);
        const float* Bs = As + A_BYTES / 4;

#pragma unroll
        for (int kk = 0; kk < 4; kk++) {
            uint32_t a[2][4];
#pragma unroll
            for (int mi = 0; mi < 2; mi++) {
                const float4 av = *(const float4*)(As + ((kk * 8 + mw * 2 + mi) * 128) + lane * 4);
                a[mi][0] = __float_as_uint(av.x);
                a[mi][1] = __float_as_uint(av.y);
                a[mi][2] = __float_as_uint(av.z);
                a[mi][3] = __float_as_uint(av.w);
            }
#pragma unroll
            for (int ni = 0; ni < 8; ni++) {
                const float* bp = Bs + (kk * 8 + tq) * BPITCH2 + nw * 64 + ni * 8 + g;
                uint32_t b0 = f2tf(bp[0]), b1 = f2tf(bp[4 * BPITCH2]);
                mma8(acc[0][ni], a[0], b0, b1);
                mma8(acc[1][ni], a[1], b0, b1);
            }
        }
        soff_c += G2_STAGE; if (soff_c == NSTAGE * G2_STAGE) soff_c = 0;
        soff_p += G2_STAGE; if (soff_p == NSTAGE * G2_STAGE) soff_p = 0;
    }

#pragma unroll
    for (int mi = 0; mi < 2; mi++) {
        int r0 = mw * 32 + mi * 16 + g;
        int t0 = tokS[r0], t1 = tokS[r0 + 8];
#pragma unroll
        for (int ni = 0; ni < 8; ni++) {
            int col = n0 + nw * 64 + ni * 8 + 2 * tq;
            if (t0 >= 0)
                *(float2*)(out + (size_t)t0 * HIDDEN + col) =
                    make_float2(acc[mi][ni][0], acc[mi][ni][1]);
            if (t1 >= 0)
                *(float2*)(out + (size_t)t1 * HIDDEN + col) =
                    make_float2(acc[mi][ni][2], acc[mi][ni][3]);
        }
    }
}

// ---------------- launch ----------------
extern "C" void kernel_launch(void* const* d_in, const int* in_sizes, int n_in,
                              void* d_out, int out_size) {
    const float* x    = (const float*)d_in[0];
    const int*   tids = (const int*)d_in[1];
    const float* gup  = (const float*)d_in[2];
    const float* down = (const float*)d_in[3];
    float*       out  = (float*)d_out;

    cudaFuncSetAttribute(pack_x_kernel, cudaFuncAttributeMaxDynamicSharedMemorySize, PX_SMEM);
    cudaFuncSetAttribute(gemm1_tc, cudaFuncAttributeMaxDynamicSharedMemorySize, G1_SMEM);
    cudaFuncSetAttribute(gemm2_tc, cudaFuncAttributeMaxDynamicSharedMemorySize, G2_SMEM);

    detect_kernel<<<1, 32>>>(tids);
    route_kernel<<<NUM_TOKENS / 256, 256>>>(tids);

    pack_x_kernel<<<dim3(HIDDEN / 128, MAX_TILES), 256, PX_SMEM>>>(x);
    gemm1_tc<<<dim3(INTER / 64, MAX_TILES), 256, G1_SMEM>>>(gup);
    gemm2_tc<<<dim3(HIDDEN / 128, MAX_TILES), 256, G2_SMEM>>>(down, out);
}

// round 8
// speedup vs baseline: 4.1481x; 1.0889x over previous
#include <cuda_runtime.h>
#include <cstdint>

#define NUM_TOKENS 8192
#define HIDDEN 4096
#define NUM_EXPERTS 8
#define INTER 2048
#define GU_COLS 4096
#define MAX_TILES 72
#define NSTAGE 3

// ---------------- scratch ----------------
__device__ int g_counts[NUM_EXPERTS];
__device__ int g_lists[NUM_EXPERTS][NUM_TOKENS];
__device__ int g_is64;
// fragment-packed activations: [tile][kfrag][mfrag 8][128 floats]
__device__ float g_xpack[(size_t)MAX_TILES * (HIDDEN / 8) * 8 * 128];
__device__ float g_interp[(size_t)MAX_TILES * (INTER / 8) * 8 * 128];

// ---------------- helpers ----------------
__device__ __forceinline__ uint32_t smem_u32(const void* p) {
    uint32_t a;
    asm("{ .reg .u64 t; cvta.to.shared.u64 t, %1; cvt.u32.u64 %0, t; }" : "=r"(a) : "l"(p));
    return a;
}
__device__ __forceinline__ uint32_t f2tf(float f) {
    uint32_t r;
    asm("cvt.rna.tf32.f32 %0, %1;" : "=r"(r) : "f"(f));
    return r;
}
__device__ __forceinline__ float4 cvt4(float4 v) {
    float4 r;
    r.x = __uint_as_float(f2tf(v.x));
    r.y = __uint_as_float(f2tf(v.y));
    r.z = __uint_as_float(f2tf(v.z));
    r.w = __uint_as_float(f2tf(v.w));
    return r;
}
__device__ __forceinline__ void mma8(float* d, const uint32_t* a, uint32_t b0, uint32_t b1) {
    asm volatile(
        "mma.sync.aligned.m16n8k8.row.col.f32.tf32.tf32.f32 "
        "{%0,%1,%2,%3},{%4,%5,%6,%7},{%8,%9},{%0,%1,%2,%3};"
        : "+f"(d[0]), "+f"(d[1]), "+f"(d[2]), "+f"(d[3])
        : "r"(a[0]), "r"(a[1]), "r"(a[2]), "r"(a[3]), "r"(b0), "r"(b1));
}
__device__ __forceinline__ void cpa16(uint32_t dst, const void* src, int srcsize) {
    asm volatile("cp.async.cg.shared.global [%0], [%1], 16, %2;" :: "r"(dst), "l"(src), "r"(srcsize));
}
__device__ __forceinline__ void cpa_commit() { asm volatile("cp.async.commit_group;" ::: "memory"); }
__device__ __forceinline__ void cpa_wait1()  { asm volatile("cp.async.wait_group 1;" ::: "memory"); }
__device__ __forceinline__ void cpa_wait0()  { asm volatile("cp.async.wait_group 0;" ::: "memory"); }

__device__ __forceinline__ float silu(float g) { return g / (1.0f + __expf(-g)); }

__device__ __forceinline__ int find_tile(int t, int* e_out, int* m0_out, int* cnt_out) {
    int acc = 0;
#pragma unroll
    for (int e = 0; e < NUM_EXPERTS; e++) {
        int c = g_counts[e];
        int nt = (c + 127) >> 7;
        if (t < acc + nt) { *e_out = e; *m0_out = (t - acc) << 7; *cnt_out = c; return 1; }
        acc += nt;
    }
    return 0;
}

// ---------------- routing ----------------
__global__ void detect_kernel(const int* __restrict__ t32) {
    if (threadIdx.x == 0) {
        int all_zero = 1;
        for (int i = 0; i < 256; i++) {
            int idx = 2 * (i * (NUM_TOKENS / 256)) + 1;
            if (t32[idx] != 0) { all_zero = 0; break; }
        }
        g_is64 = all_zero;
    }
    if (threadIdx.x < NUM_EXPERTS) g_counts[threadIdx.x] = 0;
}

__global__ void route_kernel(const int* __restrict__ t32) {
    int i = blockIdx.x * blockDim.x + threadIdx.x;
    if (i < NUM_TOKENS) {
        int v = g_is64 ? t32[2 * i] : t32[i];
        int e = v & 7;
        int p = atomicAdd(&g_counts[e], 1);
        g_lists[e][p] = i;
    }
}

// ---------------- pack_x ----------------
#define PX_PITCH 132
#define PX_SMEM (128 * PX_PITCH * 4 + 512)
__global__ __launch_bounds__(256) void pack_x_kernel(const float* __restrict__ x) {
    extern __shared__ char smem[];
    int e, m0, count;
    if (!find_tile(blockIdx.y, &e, &m0, &count)) return;
    const int kb = blockIdx.x;
    const int tid = threadIdx.x;
    int* tokS = (int*)smem;
    float* tile = (float*)(smem + 512);
    if (tid < 128) tokS[tid] = (m0 + tid < count) ? g_lists[e][m0 + tid] : -1;
    __syncthreads();
#pragma unroll
    for (int j = 0; j < 16; j++) {
        int idx = tid + j * 256;
        int r = idx >> 5, c4 = (idx & 31) * 4;
        int t = tokS[r];
        float4 v = make_float4(0.f, 0.f, 0.f, 0.f);
        if (t >= 0) v = *(const float4*)(x + (size_t)t * HIDDEN + kb * 128 + c4);
        *(float4*)(tile + r * PX_PITCH + c4) = cvt4(v);
    }
    __syncthreads();
    const int lane = tid & 31, w = tid >> 5;
    const int g = lane >> 2, tq = lane & 3;
#pragma unroll
    for (int i = 0; i < 16; i++) {
        int f = w * 16 + i;
        int mf = f & 7, kfl = f >> 3;
        const float* src = tile + (mf * 16 + g) * PX_PITCH + kfl * 8 + tq;
        float4 o;
        o.x = src[0];
        o.y = src[8 * PX_PITCH];
        o.z = src[4];
        o.w = src[8 * PX_PITCH + 4];
        size_t off = (((size_t)blockIdx.y * (HIDDEN / 8) + kb * 16 + kfl) * 8 + mf) * 128 + lane * 4;
        *(float4*)(g_xpack + off) = o;
    }
}

// smem geometry
#define A_BYTES 16384
#define BPITCH 72
#define BPITCH2 136
#define B1_BYTES (32 * BPITCH * 4)
#define B2_BYTES (32 * BPITCH2 * 4)
#define G1_STAGE (A_BYTES + 2 * B1_BYTES)
#define G2_STAGE (A_BYTES + B2_BYTES)
#define G1_SMEM (512 + NSTAGE * G1_STAGE)
#define G2_SMEM (512 + NSTAGE * G2_STAGE)

__device__ __forceinline__ void issue_Apk(uint32_t sb, int soff, const float* apack,
                                          int kc, int tid) {
    const float* src = apack + (size_t)kc * 4096;
#pragma unroll
    for (int j = 0; j < 4; j++) {
        int idx = tid + j * 256;
        cpa16(sb + 512 + soff + idx * 16, src + idx * 4, 16);
    }
}

// ---------------- GEMM1: Xpack @ GU -> silu(gate)*up -> g_interp (packed) ----------------
// warps: 2m x 4n. each warp: 4 mfrags (64 rows) x 16 cols (2 ni) per B tile.
__global__ __launch_bounds__(256, 2) void gemm1_tc(const float* __restrict__ gup) {
    extern __shared__ char smem[];
    int e, m0, count;
    if (!find_tile(blockIdx.y, &e, &m0, &count)) return;
    const int n0 = blockIdx.x * 64;
    const int t_id = blockIdx.y;

    int* tokS = (int*)smem;
    const uint32_t sb = smem_u32(smem);
    const int tid = threadIdx.x;
    const int wid = tid >> 5, lane = tid & 31;
    const int mw = wid >> 2, nw = wid & 3;
    const int g = lane >> 2, tq = lane & 3;

    if (tid < 128) tokS[tid] = (m0 + tid < count) ? g_lists[e][m0 + tid] : -1;
    __syncthreads();

    const float* apack = g_xpack + (size_t)t_id * (HIDDEN / 8) * 1024;
    const float* Bx = gup + (size_t)e * HIDDEN * GU_COLS + n0;

    auto issue_B = [&](int kc, int soff) {
#pragma unroll
        for (int h = 0; h < 2; h++) {
            int idx = tid + h * 256;
            int k = idx >> 4, n16 = (idx & 15) * 16;
            const float* gp = Bx + (size_t)(kc * 32 + k) * GU_COLS + (idx & 15) * 4;
            uint32_t base = sb + 512 + soff + A_BYTES + k * (BPITCH * 4) + n16;
            cpa16(base, gp, 16);
            cpa16(base + B1_BYTES, gp + INTER, 16);
        }
    };

    float accg[4][2][4] = {};
    float accu[4][2][4] = {};

    issue_Apk(sb, 0, apack, 0, tid);
    issue_B(0, 0);
    cpa_commit();
    issue_Apk(sb, G1_STAGE, apack, 1, tid);
    issue_B(1, G1_STAGE);
    cpa_commit();

    const int bfrag = tq * BPITCH + nw * 16 + g;   // warp-invariant B fragment base
    const int afrag = mw * 4;                      // first mfrag of this warp

    const int NK = HIDDEN / 32;
    int soff_c = 0, soff_p = 2 * G1_STAGE;
    for (int kc = 0; kc < NK; kc++) {
        if (kc + 1 < NK) cpa_wait1(); else cpa_wait0();
        __syncthreads();
        if (kc + 2 < NK) {
            issue_Apk(sb, soff_p, apack, kc + 2, tid);
            issue_B(kc + 2, soff_p);
            cpa_commit();
        }

        const float* As = (const float*)(smem + 512 + soff_c);
        const float* Bg = As + A_BYTES / 4;
        const float* Bu = Bg + 32 * BPITCH;

#pragma unroll
        for (int kk = 0; kk < 4; kk++) {
            uint32_t a[4][4];
#pragma unroll
            for (int mi = 0; mi < 4; mi++) {
                const float4 av = *(const float4*)(As + ((kk * 8 + afrag + mi) * 128) + lane * 4);
                a[mi][0] = __float_as_uint(av.x);
                a[mi][1] = __float_as_uint(av.y);
                a[mi][2] = __float_as_uint(av.z);
                a[mi][3] = __float_as_uint(av.w);
            }
#pragma unroll
            for (int ni = 0; ni < 2; ni++) {
                const float* bp = Bg + kk * (8 * BPITCH) + bfrag + ni * 8;
                uint32_t b0 = f2tf(bp[0]), b1 = f2tf(bp[4 * BPITCH]);
#pragma unroll
                for (int mi = 0; mi < 4; mi++) mma8(accg[mi][ni], a[mi], b0, b1);
                const float* up = Bu + kk * (8 * BPITCH) + bfrag + ni * 8;
                uint32_t u0 = f2tf(up[0]), u1 = f2tf(up[4 * BPITCH]);
#pragma unroll
                for (int mi = 0; mi < 4; mi++) mma8(accu[mi][ni], a[mi], u0, u1);
            }
        }
        soff_c += G1_STAGE; if (soff_c == NSTAGE * G1_STAGE) soff_c = 0;
        soff_p += G1_STAGE; if (soff_p == NSTAGE * G1_STAGE) soff_p = 0;
    }

    // fused epilogue -> fragment-packed g_interp (tf32-rounded)
#pragma unroll
    for (int mi = 0; mi < 4; mi++) {
        int mf = mw * 4 + mi;
        int r0 = mw * 64 + mi * 16 + g;
        int t0 = tokS[r0], t1 = tokS[r0 + 8];
#pragma unroll
        for (int ni = 0; ni < 2; ni++) {
            int c = nw * 16 + ni * 8 + 2 * tq;
            int kf = (n0 + c) >> 3;
            int hc2 = ((c >> 2) & 1) * 2;
            int tq0 = c & 3;
            float* base = g_interp + (((size_t)t_id * (INTER / 8) + kf) * 8 + mf) * 128;
            if (t0 >= 0) {
                base[(g * 4 + tq0) * 4 + hc2] =
                    __uint_as_float(f2tf(silu(accg[mi][ni][0]) * accu[mi][ni][0]));
                base[(g * 4 + tq0 + 1) * 4 + hc2] =
                    __uint_as_float(f2tf(silu(accg[mi][ni][1]) * accu[mi][ni][1]));
            }
            if (t1 >= 0) {
                base[(g * 4 + tq0) * 4 + 1 + hc2] =
                    __uint_as_float(f2tf(silu(accg[mi][ni][2]) * accu[mi][ni][2]));
                base[(g * 4 + tq0 + 1) * 4 + 1 + hc2] =
                    __uint_as_float(f2tf(silu(accg[mi][ni][3]) * accu[mi][ni][3]));
            }
        }
    }
}

// ---------------- GEMM2: g_interp @ down -> out  (BN=128, warps 2m x 4n) ----------------
__global__ __launch_bounds__(256, 2) void gemm2_tc(const float* __restrict__ down,
                                                   float* __restrict__ out) {
    extern __shared__ char smem[];
    int e, m0, count;
    if (!find_tile(blockIdx.y, &e, &m0, &count)) return;
    const int n0 = blockIdx.x * 128;
    const int t_id = blockIdx.y;

    int* tokS = (int*)smem;
    const uint32_t sb = smem_u32(smem);
    const int tid = threadIdx.x;
    const int wid = tid >> 5, lane = tid & 31;
    const int mw = wid >> 2, nw = wid & 3;
    const int g = lane >> 2, tq = lane & 3;

    if (tid < 128) tokS[tid] = (m0 + tid < count) ? g_lists[e][m0 + tid] : -1;
    __syncthreads();

    const float* apack = g_interp + (size_t)t_id * (INTER / 8) * 1024;
    const float* Bx = down + (size_t)e * INTER * HIDDEN + n0;

    auto issue_B = [&](int kc, int soff) {
#pragma unroll
        for (int h = 0; h < 4; h++) {
            int idx = tid + h * 256;
            int k = idx >> 5, c4 = (idx & 31) * 4;
            const float* gp = Bx + (size_t)(kc * 32 + k) * HIDDEN + c4;
            uint32_t base = sb + 512 + soff + A_BYTES + k * (BPITCH2 * 4) + c4 * 4;
            cpa16(base, gp, 16);
        }
    };

    float acc[4][4][4] = {};

    issue_Apk(sb, 0, apack, 0, tid);
    issue_B(0, 0);
    cpa_commit();
    issue_Apk(sb, G2_STAGE, apack, 1, tid);
    issue_B(1, G2_STAGE);
    cpa_commit();

    const int bfrag = tq * BPITCH2 + nw * 32 + g;
    const int afrag = mw * 4;

    const int NK = INTER / 32;
    int soff_c = 0, soff_p = 2 * G2_STAGE;
    for (int kc = 0; kc < NK; kc++) {
        if (kc + 1 < NK) cpa_wait1(); else cpa_wait0();
        __syncthreads();
        if (kc + 2 < NK) {
            issue_Apk(sb, soff_p, apack, kc + 2, tid);
            issue_B(kc + 2, soff_p);
            cpa_commit();
        }

        const float* As = (const float*)(smem + 512 + soff_c);
        const float* Bs = As + A_BYTES / 4;

#pragma unroll
        for (int kk = 0; kk < 4; kk++) {
            uint32_t a[4][4];
#pragma unroll
            for (int mi = 0; mi < 4; mi++) {
                const float4 av = *(const float4*)(As + ((kk * 8 + afrag + mi) * 128) + lane * 4);
                a[mi][0] = __float_as_uint(av.x);
                a[mi][1] = __float_as_uint(av.y);
                a[mi][2] = __float_as_uint(av.z);
                a[mi][3] = __float_as_uint(av.w);
            }
#pragma unroll
            for (int ni = 0; ni < 4; ni++) {
                const float* bp = Bs + kk * (8 * BPITCH2) + bfrag + ni * 8;
                uint32_t b0 = f2tf(bp[0]), b1 = f2tf(bp[4 * BPITCH2]);
#pragma unroll
                for (int mi = 0; mi < 4; mi++) mma8(acc[mi][ni], a[mi], b0, b1);
            }
        }
        soff_c += G2_STAGE; if (soff_c == NSTAGE * G2_STAGE) soff_c = 0;
        soff_p += G2_STAGE; if (soff_p == NSTAGE * G2_STAGE) soff_p = 0;
    }

#pragma unroll
    for (int mi = 0; mi < 4; mi++) {
        int r0 = mw * 64 + mi * 16 + g;
        int t0 = tokS[r0], t1 = tokS[r0 + 8];
#pragma unroll
        for (int ni = 0; ni < 4; ni++) {
            int col = n0 + nw * 32 + ni * 8 + 2 * tq;
            if (t0 >= 0)
                *(float2*)(out + (size_t)t0 * HIDDEN + col) =
                    make_float2(acc[mi][ni][0], acc[mi][ni][1]);
            if (t1 >= 0)
                *(float2*)(out + (size_t)t1 * HIDDEN + col) =
                    make_float2(acc[mi][ni][2], acc[mi][ni][3]);
        }
    }
}

// ---------------- launch ----------------
extern "C" void kernel_launch(void* const* d_in, const int* in_sizes, int n_in,
                              void* d_out, int out_size) {
    const float* x    = (const float*)d_in[0];
    const int*   tids = (const int*)d_in[1];
    const float* gup  = (const float*)d_in[2];
    const float* down = (const float*)d_in[3];
    float*       out  = (float*)d_out;

    cudaFuncSetAttribute(pack_x_kernel, cudaFuncAttributeMaxDynamicSharedMemorySize, PX_SMEM);
    cudaFuncSetAttribute(gemm1_tc, cudaFuncAttributeMaxDynamicSharedMemorySize, G1_SMEM);
    cudaFuncSetAttribute(gemm2_tc, cudaFuncAttributeMaxDynamicSharedMemorySize, G2_SMEM);

    detect_kernel<<<1, 32>>>(tids);
    route_kernel<<<NUM_TOKENS / 256, 256>>>(tids);

    pack_x_kernel<<<dim3(HIDDEN / 128, MAX_TILES), 256, PX_SMEM>>>(x);
    gemm1_tc<<<dim3(INTER / 64, MAX_TILES), 256, G1_SMEM>>>(gup);
    gemm2_tc<<<dim3(HIDDEN / 128, MAX_TILES), 256, G2_SMEM>>>(down, out);
}

// round 9
// speedup vs baseline: 4.1504x; 1.0006x over previous
#include <cuda_runtime.h>
#include <cstdint>

#define NUM_TOKENS 8192
#define HIDDEN 4096
#define NUM_EXPERTS 8
#define INTER 2048
#define GU_COLS 4096
#define MAX_TILES 72
#define NSTAGE 3

// ---------------- scratch ----------------
__device__ int g_counts[NUM_EXPERTS];
__device__ int g_lists[NUM_EXPERTS][NUM_TOKENS];
__device__ int g_is64;
// fragment-packed activations: [tile][kfrag][mfrag 8][128 floats]
__device__ float g_xpack[(size_t)MAX_TILES * (HIDDEN / 8) * 8 * 128];
__device__ float g_interp[(size_t)MAX_TILES * (INTER / 8) * 8 * 128];

// ---------------- helpers ----------------
__device__ __forceinline__ uint32_t smem_u32(const void* p) {
    uint32_t a;
    asm("{ .reg .u64 t; cvta.to.shared.u64 t, %1; cvt.u32.u64 %0, t; }" : "=r"(a) : "l"(p));
    return a;
}
__device__ __forceinline__ uint32_t f2tf(float f) {
    uint32_t r;
    asm("cvt.rna.tf32.f32 %0, %1;" : "=r"(r) : "f"(f));
    return r;
}
__device__ __forceinline__ float4 cvt4(float4 v) {
    float4 r;
    r.x = __uint_as_float(f2tf(v.x));
    r.y = __uint_as_float(f2tf(v.y));
    r.z = __uint_as_float(f2tf(v.z));
    r.w = __uint_as_float(f2tf(v.w));
    return r;
}
__device__ __forceinline__ void mma8(float* d, const uint32_t* a, uint32_t b0, uint32_t b1) {
    asm volatile(
        "mma.sync.aligned.m16n8k8.row.col.f32.tf32.tf32.f32 "
        "{%0,%1,%2,%3},{%4,%5,%6,%7},{%8,%9},{%0,%1,%2,%3};"
        : "+f"(d[0]), "+f"(d[1]), "+f"(d[2]), "+f"(d[3])
        : "r"(a[0]), "r"(a[1]), "r"(a[2]), "r"(a[3]), "r"(b0), "r"(b1));
}
__device__ __forceinline__ void cpa16(uint32_t dst, const void* src, int srcsize) {
    asm volatile("cp.async.cg.shared.global [%0], [%1], 16, %2;" :: "r"(dst), "l"(src), "r"(srcsize));
}
__device__ __forceinline__ void cpa_commit() { asm volatile("cp.async.commit_group;" ::: "memory"); }
__device__ __forceinline__ void cpa_wait1()  { asm volatile("cp.async.wait_group 1;" ::: "memory"); }
__device__ __forceinline__ void cpa_wait0()  { asm volatile("cp.async.wait_group 0;" ::: "memory"); }

__device__ __forceinline__ float silu(float g) { return g / (1.0f + __expf(-g)); }

__device__ __forceinline__ int find_tile(int t, int* e_out, int* m0_out, int* cnt_out) {
    int acc = 0;
#pragma unroll
    for (int e = 0; e < NUM_EXPERTS; e++) {
        int c = g_counts[e];
        int nt = (c + 127) >> 7;
        if (t < acc + nt) { *e_out = e; *m0_out = (t - acc) << 7; *cnt_out = c; return 1; }
        acc += nt;
    }
    return 0;
}

// ---------------- routing ----------------
__global__ void detect_kernel(const int* __restrict__ t32) {
    if (threadIdx.x == 0) {
        int all_zero = 1;
        for (int i = 0; i < 256; i++) {
            int idx = 2 * (i * (NUM_TOKENS / 256)) + 1;
            if (t32[idx] != 0) { all_zero = 0; break; }
        }
        g_is64 = all_zero;
    }
    if (threadIdx.x < NUM_EXPERTS) g_counts[threadIdx.x] = 0;
}

__global__ void route_kernel(const int* __restrict__ t32) {
    int i = blockIdx.x * blockDim.x + threadIdx.x;
    if (i < NUM_TOKENS) {
        int v = g_is64 ? t32[2 * i] : t32[i];
        int e = v & 7;
        int p = atomicAdd(&g_counts[e], 1);
        g_lists[e][p] = i;
    }
}

// ---------------- pack_x ----------------
#define PX_PITCH 132
#define PX_SMEM (128 * PX_PITCH * 4 + 512)
__global__ __launch_bounds__(256) void pack_x_kernel(const float* __restrict__ x) {
    extern __shared__ char smem[];
    int e, m0, count;
    if (!find_tile(blockIdx.y, &e, &m0, &count)) return;
    const int kb = blockIdx.x;
    const int tid = threadIdx.x;
    int* tokS = (int*)smem;
    float* tile = (float*)(smem + 512);
    if (tid < 128) tokS[tid] = (m0 + tid < count) ? g_lists[e][m0 + tid] : -1;
    __syncthreads();
#pragma unroll
    for (int j = 0; j < 16; j++) {
        int idx = tid + j * 256;
        int r = idx >> 5, c4 = (idx & 31) * 4;
        int t = tokS[r];
        float4 v = make_float4(0.f, 0.f, 0.f, 0.f);
        if (t >= 0) v = *(const float4*)(x + (size_t)t * HIDDEN + kb * 128 + c4);
        *(float4*)(tile + r * PX_PITCH + c4) = cvt4(v);
    }
    __syncthreads();
    const int lane = tid & 31, w = tid >> 5;
    const int g = lane >> 2, tq = lane & 3;
#pragma unroll
    for (int i = 0; i < 16; i++) {
        int f = w * 16 + i;
        int mf = f & 7, kfl = f >> 3;
        const float* src = tile + (mf * 16 + g) * PX_PITCH + kfl * 8 + tq;
        float4 o;
        o.x = src[0];
        o.y = src[8 * PX_PITCH];
        o.z = src[4];
        o.w = src[8 * PX_PITCH + 4];
        size_t off = (((size_t)blockIdx.y * (HIDDEN / 8) + kb * 16 + kfl) * 8 + mf) * 128 + lane * 4;
        *(float4*)(g_xpack + off) = o;
    }
}

// smem geometry
#define A_BYTES 16384
#define BPITCH 72
#define BPITCH2 136
#define B1_BYTES (32 * BPITCH * 4)
#define B2_BYTES (32 * BPITCH2 * 4)
#define G1_STAGE (A_BYTES + 2 * B1_BYTES)
#define G2_STAGE (A_BYTES + B2_BYTES)
#define G1_SMEM (512 + NSTAGE * G1_STAGE)
#define G2_SMEM (512 + NSTAGE * G2_STAGE)

__device__ __forceinline__ void issue_Apk(uint32_t sb, int soff, const float* apack,
                                          int kc, int tid) {
    const float* src = apack + (size_t)kc * 4096;
#pragma unroll
    for (int j = 0; j < 4; j++) {
        int idx = tid + j * 256;
        cpa16(sb + 512 + soff + idx * 16, src + idx * 4, 16);
    }
}

// ---------------- GEMM1: Xpack @ GU -> silu(gate)*up -> g_interp (packed) ----------------
// warps: 2m x 4n. B fragments register-double-buffered across kk; A loaded at use.
__global__ __launch_bounds__(256, 2) void gemm1_tc(const float* __restrict__ gup) {
    extern __shared__ char smem[];
    int e, m0, count;
    if (!find_tile(blockIdx.y, &e, &m0, &count)) return;
    const int n0 = blockIdx.x * 64;
    const int t_id = blockIdx.y;

    int* tokS = (int*)smem;
    const uint32_t sb = smem_u32(smem);
    const int tid = threadIdx.x;
    const int wid = tid >> 5, lane = tid & 31;
    const int mw = wid >> 2, nw = wid & 3;
    const int g = lane >> 2, tq = lane & 3;

    if (tid < 128) tokS[tid] = (m0 + tid < count) ? g_lists[e][m0 + tid] : -1;
    __syncthreads();

    const float* apack = g_xpack + (size_t)t_id * (HIDDEN / 8) * 1024;
    const float* Bx = gup + (size_t)e * HIDDEN * GU_COLS + n0;

    auto issue_B = [&](int kc, int soff) {
#pragma unroll
        for (int h = 0; h < 2; h++) {
            int idx = tid + h * 256;
            int k = idx >> 4, n16 = (idx & 15) * 16;
            const float* gp = Bx + (size_t)(kc * 32 + k) * GU_COLS + (idx & 15) * 4;
            uint32_t base = sb + 512 + soff + A_BYTES + k * (BPITCH * 4) + n16;
            cpa16(base, gp, 16);
            cpa16(base + B1_BYTES, gp + INTER, 16);
        }
    };

    float accg[4][2][4] = {};
    float accu[4][2][4] = {};

    issue_Apk(sb, 0, apack, 0, tid);
    issue_B(0, 0);
    cpa_commit();
    issue_Apk(sb, G1_STAGE, apack, 1, tid);
    issue_B(1, G1_STAGE);
    cpa_commit();

    const int bfrag = tq * BPITCH + nw * 16 + g;
    const int afrag = mw * 4;

    const int NK = HIDDEN / 32;
    int soff_c = 0, soff_p = 2 * G1_STAGE;
    for (int kc = 0; kc < NK; kc++) {
        if (kc + 1 < NK) cpa_wait1(); else cpa_wait0();
        __syncthreads();
        if (kc + 2 < NK) {
            issue_Apk(sb, soff_p, apack, kc + 2, tid);
            issue_B(kc + 2, soff_p);
            cpa_commit();
        }

        const float* As = (const float*)(smem + 512 + soff_c);
        const float* Bg = As + A_BYTES / 4;
        const float* Bu = Bg + 32 * BPITCH;

        uint32_t bg[2][2][2], bu[2][2][2];
        // preload kk=0 B fragments
#pragma unroll
        for (int ni = 0; ni < 2; ni++) {
            const float* bp = Bg + bfrag + ni * 8;
            bg[0][ni][0] = f2tf(bp[0]); bg[0][ni][1] = f2tf(bp[4 * BPITCH]);
            const float* up = Bu + bfrag + ni * 8;
            bu[0][ni][0] = f2tf(up[0]); bu[0][ni][1] = f2tf(up[4 * BPITCH]);
        }

#pragma unroll
        for (int kk = 0; kk < 4; kk++) {
            const int cur = kk & 1, nxt = cur ^ 1;
            if (kk < 3) {
#pragma unroll
                for (int ni = 0; ni < 2; ni++) {
                    const float* bp = Bg + (kk + 1) * (8 * BPITCH) + bfrag + ni * 8;
                    bg[nxt][ni][0] = f2tf(bp[0]); bg[nxt][ni][1] = f2tf(bp[4 * BPITCH]);
                    const float* up = Bu + (kk + 1) * (8 * BPITCH) + bfrag + ni * 8;
                    bu[nxt][ni][0] = f2tf(up[0]); bu[nxt][ni][1] = f2tf(up[4 * BPITCH]);
                }
            }
#pragma unroll
            for (int mi = 0; mi < 4; mi++) {
                const float4 av = *(const float4*)(As + ((kk * 8 + afrag + mi) * 128) + lane * 4);
                uint32_t a[4];
                a[0] = __float_as_uint(av.x);
                a[1] = __float_as_uint(av.y);
                a[2] = __float_as_uint(av.z);
                a[3] = __float_as_uint(av.w);
                mma8(accg[mi][0], a, bg[cur][0][0], bg[cur][0][1]);
                mma8(accg[mi][1], a, bg[cur][1][0], bg[cur][1][1]);
                mma8(accu[mi][0], a, bu[cur][0][0], bu[cur][0][1]);
                mma8(accu[mi][1], a, bu[cur][1][0], bu[cur][1][1]);
            }
        }
        soff_c += G1_STAGE; if (soff_c == NSTAGE * G1_STAGE) soff_c = 0;
        soff_p += G1_STAGE; if (soff_p == NSTAGE * G1_STAGE) soff_p = 0;
    }

    // fused epilogue -> fragment-packed g_interp (tf32-rounded)
#pragma unroll
    for (int mi = 0; mi < 4; mi++) {
        int mf = mw * 4 + mi;
        int r0 = mw * 64 + mi * 16 + g;
        int t0 = tokS[r0], t1 = tokS[r0 + 8];
#pragma unroll
        for (int ni = 0; ni < 2; ni++) {
            int c = nw * 16 + ni * 8 + 2 * tq;
            int kf = (n0 + c) >> 3;
            int hc2 = ((c >> 2) & 1) * 2;
            int tq0 = c & 3;
            float* base = g_interp + (((size_t)t_id * (INTER / 8) + kf) * 8 + mf) * 128;
            if (t0 >= 0) {
                base[(g * 4 + tq0) * 4 + hc2] =
                    __uint_as_float(f2tf(silu(accg[mi][ni][0]) * accu[mi][ni][0]));
                base[(g * 4 + tq0 + 1) * 4 + hc2] =
                    __uint_as_float(f2tf(silu(accg[mi][ni][1]) * accu[mi][ni][1]));
            }
            if (t1 >= 0) {
                base[(g * 4 + tq0) * 4 + 1 + hc2] =
                    __uint_as_float(f2tf(silu(accg[mi][ni][2]) * accu[mi][ni][2]));
                base[(g * 4 + tq0 + 1) * 4 + 1 + hc2] =
                    __uint_as_float(f2tf(silu(accg[mi][ni][3]) * accu[mi][ni][3]));
            }
        }
    }
}

// ---------------- GEMM2: g_interp @ down -> out  (BN=128, warps 2m x 4n) ----------------
__global__ __launch_bounds__(256, 2) void gemm2_tc(const float* __restrict__ down,
                                                   float* __restrict__ out) {
    extern __shared__ char smem[];
    int e, m0, count;
    if (!find_tile(blockIdx.y, &e, &m0, &count)) return;
    const int n0 = blockIdx.x * 128;
    const int t_id = blockIdx.y;

    int* tokS = (int*)smem;
    const uint32_t sb = smem_u32(smem);
    const int tid = threadIdx.x;
    const int wid = tid >> 5, lane = tid & 31;
    const int mw = wid >> 2, nw = wid & 3;
    const int g = lane >> 2, tq = lane & 3;

    if (tid < 128) tokS[tid] = (m0 + tid < count) ? g_lists[e][m0 + tid] : -1;
    __syncthreads();

    const float* apack = g_interp + (size_t)t_id * (INTER / 8) * 1024;
    const float* Bx = down + (size_t)e * INTER * HIDDEN + n0;

    auto issue_B = [&](int kc, int soff) {
#pragma unroll
        for (int h = 0; h < 4; h++) {
            int idx = tid + h * 256;
            int k = idx >> 5, c4 = (idx & 31) * 4;
            const float* gp = Bx + (size_t)(kc * 32 + k) * HIDDEN + c4;
            uint32_t base = sb + 512 + soff + A_BYTES + k * (BPITCH2 * 4) + c4 * 4;
            cpa16(base, gp, 16);
        }
    };

    float acc[4][4][4] = {};

    issue_Apk(sb, 0, apack, 0, tid);
    issue_B(0, 0);
    cpa_commit();
    issue_Apk(sb, G2_STAGE, apack, 1, tid);
    issue_B(1, G2_STAGE);
    cpa_commit();

    const int bfrag = tq * BPITCH2 + nw * 32 + g;
    const int afrag = mw * 4;

    const int NK = INTER / 32;
    int soff_c = 0, soff_p = 2 * G2_STAGE;
    for (int kc = 0; kc < NK; kc++) {
        if (kc + 1 < NK) cpa_wait1(); else cpa_wait0();
        __syncthreads();
        if (kc + 2 < NK) {
            issue_Apk(sb, soff_p, apack, kc + 2, tid);
            issue_B(kc + 2, soff_p);
            cpa_commit();
        }

        const float* As = (const float*)(smem + 512 + soff_c);
        const float* Bs = As + A_BYTES / 4;

        uint32_t bb[2][4][2];
#pragma unroll
        for (int ni = 0; ni < 4; ni++) {
            const float* bp = Bs + bfrag + ni * 8;
            bb[0][ni][0] = f2tf(bp[0]); bb[0][ni][1] = f2tf(bp[4 * BPITCH2]);
        }

#pragma unroll
        for (int kk = 0; kk < 4; kk++) {
            const int cur = kk & 1, nxt = cur ^ 1;
            if (kk < 3) {
#pragma unroll
                for (int ni = 0; ni < 4; ni++) {
                    const float* bp = Bs + (kk + 1) * (8 * BPITCH2) + bfrag + ni * 8;
                    bb[nxt][ni][0] = f2tf(bp[0]); bb[nxt][ni][1] = f2tf(bp[4 * BPITCH2]);
                }
            }
#pragma unroll
            for (int mi = 0; mi < 4; mi++) {
                const float4 av = *(const float4*)(As + ((kk * 8 + afrag + mi) * 128) + lane * 4);
                uint32_t a[4];
                a[0] = __float_as_uint(av.x);
                a[1] = __float_as_uint(av.y);
                a[2] = __float_as_uint(av.z);
                a[3] = __float_as_uint(av.w);
#pragma unroll
                for (int ni = 0; ni < 4; ni++)
                    mma8(acc[mi][ni], a, bb[cur][ni][0], bb[cur][ni][1]);
            }
        }
        soff_c += G2_STAGE; if (soff_c == NSTAGE * G2_STAGE) soff_c = 0;
        soff_p += G2_STAGE; if (soff_p == NSTAGE * G2_STAGE) soff_p = 0;
    }

#pragma unroll
    for (int mi = 0; mi < 4; mi++) {
        int r0 = mw * 64 + mi * 16 + g;
        int t0 = tokS[r0], t1 = tokS[r0 + 8];
#pragma unroll
        for (int ni = 0; ni < 4; ni++) {
            int col = n0 + nw * 32 + ni * 8 + 2 * tq;
            if (t0 >= 0)
                *(float2*)(out + (size_t)t0 * HIDDEN + col) =
                    make_float2(acc[mi][ni][0], acc[mi][ni][1]);
            if (t1 >= 0)
                *(float2*)(out + (size_t)t1 * HIDDEN + col) =
                    make_float2(acc[mi][ni][2], acc[mi][ni][3]);
        }
    }
}

// ---------------- launch ----------------
extern "C" void kernel_launch(void* const* d_in, const int* in_sizes, int n_in,
                              void* d_out, int out_size) {
    const float* x    = (const float*)d_in[0];
    const int*   tids = (const int*)d_in[1];
    const float* gup  = (const float*)d_in[2];
    const float* down = (const float*)d_in[3];
    float*       out  = (float*)d_out;

    cudaFuncSetAttribute(pack_x_kernel, cudaFuncAttributeMaxDynamicSharedMemorySize, PX_SMEM);
    cudaFuncSetAttribute(gemm1_tc, cudaFuncAttributeMaxDynamicSharedMemorySize, G1_SMEM);
    cudaFuncSetAttribute(gemm2_tc, cudaFuncAttributeMaxDynamicSharedMemorySize, G2_SMEM);

    detect_kernel<<<1, 32>>>(tids);
    route_kernel<<<NUM_TOKENS / 256, 256>>>(tids);

    pack_x_kernel<<<dim3(HIDDEN / 128, MAX_TILES), 256, PX_SMEM>>>(x);
    gemm1_tc<<<dim3(INTER / 64, MAX_TILES), 256, G1_SMEM>>>(gup);
    gemm2_tc<<<dim3(HIDDEN / 128, MAX_TILES), 256, G2_SMEM>>>(down, out);
}